// round 1
// baseline (speedup 1.0000x reference)
#include <cuda_runtime.h>
#include <math.h>

#define DIMS 1024
#define FFD  4096
#define BATCH 4
#define SEQ  4096
#define ROWS (BATCH*SEQ)   // 16384
#define NF   513           // rfft bins for N=1024

// ---------------- scratch (device globals; no allocation allowed) ----------------
__device__ float  g_q [(size_t)ROWS*DIMS];
__device__ float  g_k [(size_t)ROWS*DIMS];
__device__ float  g_x1[(size_t)ROWS*DIMS];
__device__ float  g_ff[(size_t)ROWS*DIMS];
__device__ float  g_h [(size_t)ROWS*FFD];
__device__ float2 g_kx[(size_t)ROWS*NF];
__device__ float2 g_qf[(size_t)ROWS*NF];
__device__ float2 g_sf[BATCH*NF];

// ---------------- helpers ----------------
__device__ __forceinline__ float2 cmulf(float2 a, float2 b) {
    return make_float2(a.x*b.x - a.y*b.y, a.x*b.y + a.y*b.x);
}

__device__ __forceinline__ float block_sum512(float v, volatile float* red) {
    int t = threadIdx.x;
    #pragma unroll
    for (int o = 16; o; o >>= 1) v += __shfl_xor_sync(0xffffffffu, v, o);
    if ((t & 31) == 0) red[t >> 5] = v;
    __syncthreads();
    if (t == 0) {
        float s = 0.f;
        #pragma unroll
        for (int i = 0; i < 16; i++) s += red[i];
        red[0] = s;
    }
    __syncthreads();
    float r = red[0];
    __syncthreads();
    return r;
}

// 1024-pt complex Stockham radix-2 FFT, 512 threads, one butterfly per thread
// per stage. Caller must __syncthreads() after filling bufA. Result returned
// (== bufA after 10 stages).
__device__ __forceinline__ float2* fft1024(float2* bufA, float2* bufB,
                                           const float2* tw, int t) {
    float2* src = bufA; float2* dst = bufB;
    #pragma unroll
    for (int m = 1; m <= 512; m <<= 1) {
        float2 a = src[t];
        float2 b = src[t + 512];
        int jm = t & ~(m - 1);
        float2 w = tw[jm];
        float2 s = make_float2(a.x + b.x, a.y + b.y);
        float2 d = make_float2(a.x - b.x, a.y - b.y);
        float2 r = make_float2(d.x*w.x - d.y*w.y, d.x*w.y + d.y*w.x);
        dst[t + jm]     = s;
        dst[t + jm + m] = r;
        __syncthreads();
        float2* tmp = src; src = dst; dst = tmp;
    }
    return src;  // bufA after 10 stages
}

// ---------------- GEMM: C[M,N] = A[MxK] * B[NxK]^T + bias, optional relu ----------------
// A row-major (lda=K), B row-major (ldb=K). 128x128x16 tile, 8x8 per thread.
template<int RELU>
__global__ void __launch_bounds__(256) gemm_nt(
    const float* __restrict__ A, const float* __restrict__ B,
    const float* __restrict__ bias, float* __restrict__ C,
    int M, int N, int K)
{
    __shared__ float As[16][132];
    __shared__ float Bs[16][132];
    const int tid = threadIdx.x;
    const int tx = tid & 15;
    const int ty = tid >> 4;
    const float* Ab = A + (size_t)blockIdx.y * 128 * K;
    const float* Bb = B + (size_t)blockIdx.x * 128 * K;

    const int lrow = tid >> 2;        // 0..63
    const int lcol = (tid & 3) << 2;  // 0,4,8,12

    float acc[8][8];
    #pragma unroll
    for (int i = 0; i < 8; i++)
        #pragma unroll
        for (int j = 0; j < 8; j++) acc[i][j] = 0.f;

    for (int k0 = 0; k0 < K; k0 += 16) {
        float4 a0 = *(const float4*)(Ab + (size_t)lrow       * K + k0 + lcol);
        float4 a1 = *(const float4*)(Ab + (size_t)(lrow + 64)* K + k0 + lcol);
        float4 b0 = *(const float4*)(Bb + (size_t)lrow       * K + k0 + lcol);
        float4 b1 = *(const float4*)(Bb + (size_t)(lrow + 64)* K + k0 + lcol);
        __syncthreads();
        As[lcol+0][lrow] = a0.x; As[lcol+1][lrow] = a0.y;
        As[lcol+2][lrow] = a0.z; As[lcol+3][lrow] = a0.w;
        As[lcol+0][lrow+64] = a1.x; As[lcol+1][lrow+64] = a1.y;
        As[lcol+2][lrow+64] = a1.z; As[lcol+3][lrow+64] = a1.w;
        Bs[lcol+0][lrow] = b0.x; Bs[lcol+1][lrow] = b0.y;
        Bs[lcol+2][lrow] = b0.z; Bs[lcol+3][lrow] = b0.w;
        Bs[lcol+0][lrow+64] = b1.x; Bs[lcol+1][lrow+64] = b1.y;
        Bs[lcol+2][lrow+64] = b1.z; Bs[lcol+3][lrow+64] = b1.w;
        __syncthreads();
        #pragma unroll
        for (int kk = 0; kk < 16; kk++) {
            float4 ar0 = *(const float4*)&As[kk][ty*8];
            float4 ar1 = *(const float4*)&As[kk][ty*8+4];
            float4 br0 = *(const float4*)&Bs[kk][tx*8];
            float4 br1 = *(const float4*)&Bs[kk][tx*8+4];
            float ar[8] = {ar0.x, ar0.y, ar0.z, ar0.w, ar1.x, ar1.y, ar1.z, ar1.w};
            float br[8] = {br0.x, br0.y, br0.z, br0.w, br1.x, br1.y, br1.z, br1.w};
            #pragma unroll
            for (int i = 0; i < 8; i++)
                #pragma unroll
                for (int j = 0; j < 8; j++)
                    acc[i][j] += ar[i] * br[j];
        }
    }

    const int crow = blockIdx.y * 128 + ty * 8;
    const int ccol = blockIdx.x * 128 + tx * 8;
    float bi[8];
    #pragma unroll
    for (int j = 0; j < 8; j++) bi[j] = bias[ccol + j];
    #pragma unroll
    for (int i = 0; i < 8; i++) {
        float v[8];
        #pragma unroll
        for (int j = 0; j < 8; j++) {
            v[j] = acc[i][j] + bi[j];
            if (RELU) v[j] = fmaxf(v[j], 0.f);
        }
        float* cp = C + (size_t)(crow + i) * N + ccol;
        *(float4*)(cp)     = make_float4(v[0], v[1], v[2], v[3]);
        *(float4*)(cp + 4) = make_float4(v[4], v[5], v[6], v[7]);
    }
}

// ---------------- forward FFTs: LN(q), LN(k); Kx = Xf*Kf; Qf ----------------
__global__ void __launch_bounds__(512) fft_fwd_kernel(
    const float* __restrict__ x,
    const float* __restrict__ gq, const float* __restrict__ betaq,
    const float* __restrict__ gk, const float* __restrict__ betak)
{
    const int row = blockIdx.x;
    const int t = threadIdx.x;
    __shared__ float2 tw[512];
    __shared__ float2 bufA[1024];
    __shared__ float2 bufB[1024];
    __shared__ float  red[16];

    {   // tw[i] = exp(-2*pi*i*t/1024)
        float s_, c_;
        sincospif((float)t * (1.0f/512.0f), &s_, &c_);
        tw[t] = make_float2(c_, -s_);
    }

    const float* xr = x   + (size_t)row * DIMS;
    const float* qr = g_q + (size_t)row * DIMS;
    const float* kr = g_k + (size_t)row * DIMS;
    float x0 = xr[t], x1 = xr[t+512];
    float q0 = qr[t], q1 = qr[t+512];
    float k0 = kr[t], k1 = kr[t+512];

    const float invN = 1.0f / 1024.0f;
    float qs  = block_sum512(q0 + q1, red);
    float qss = block_sum512(q0*q0 + q1*q1, red);
    float ks  = block_sum512(k0 + k1, red);
    float kss = block_sum512(k0*k0 + k1*k1, red);
    float mq = qs * invN, vq = qss * invN - mq*mq;
    float rq = rsqrtf(vq + 1e-5f);
    float mk = ks * invN, vk = kss * invN - mk*mk;
    float rk = rsqrtf(vk + 1e-5f);
    float qn0 = (q0 - mq) * rq * gq[t]     + betaq[t];
    float qn1 = (q1 - mq) * rq * gq[t+512] + betaq[t+512];
    float kn0 = (k0 - mk) * rk * gk[t]     + betak[t];
    float kn1 = (k1 - mk) * rk * gk[t+512] + betak[t+512];

    // FFT of z = x + i*kn (two real FFTs at once)
    bufA[t]     = make_float2(x0, kn0);
    bufA[t+512] = make_float2(x1, kn1);
    __syncthreads();
    float2* Z = fft1024(bufA, bufB, tw, t);

    {   // split: Xf = (Z[j]+conj(Z[N-j]))/2 ; Kf = (Z[j]-conj(Z[N-j]))/(2i)
        float2 z  = Z[t];
        float2 zn = Z[(1024 - t) & 1023];
        float2 xf = make_float2(0.5f*(z.x + zn.x), 0.5f*(z.y - zn.y));
        float2 df = make_float2(z.x - zn.x, z.y + zn.y);
        float2 kf = make_float2(0.5f*df.y, -0.5f*df.x);
        g_kx[(size_t)row*NF + t] = cmulf(xf, kf);
        if (t == 0) {
            float2 z5 = Z[512];
            g_kx[(size_t)row*NF + 512] = make_float2(z5.x * z5.y, 0.f);
        }
    }
    __syncthreads();

    // FFT of q (real)
    bufA[t]     = make_float2(qn0, 0.f);
    bufA[t+512] = make_float2(qn1, 0.f);
    __syncthreads();
    float2* Q = fft1024(bufA, bufB, tw, t);
    g_qf[(size_t)row*NF + t] = Q[t];
    if (t == 0) g_qf[(size_t)row*NF + 512] = Q[512];
}

// ---------------- reduce S_freq[b] = sum_s Kx[b,s] ----------------
__global__ void __launch_bounds__(256) reduce_s_kernel() {
    const int b = blockIdx.x;   // 0..3
    const int j = blockIdx.y;   // 0..512
    const int t = threadIdx.x;  // 256
    float2 acc = make_float2(0.f, 0.f);
    const float2* p = g_kx + (size_t)b * SEQ * NF + j;
    for (int s = t; s < SEQ; s += 256) {
        float2 v = p[(size_t)s * NF];
        acc.x += v.x; acc.y += v.y;
    }
    __shared__ float2 red[256];
    red[t] = acc;
    __syncthreads();
    for (int o = 128; o; o >>= 1) {
        if (t < o) { red[t].x += red[t+o].x; red[t].y += red[t+o].y; }
        __syncthreads();
    }
    if (t == 0) g_sf[b * NF + j] = red[0];
}

// ---------------- inverse FFT of mixF = Kx + S*conj(Qf); LN(x + mix) ----------------
__global__ void __launch_bounds__(512) fft_inv_ln_kernel(
    const float* __restrict__ x,
    const float* __restrict__ g0, const float* __restrict__ beta0)
{
    const int row = blockIdx.x;
    const int b = row >> 12;  // row / SEQ
    const int t = threadIdx.x;
    __shared__ float2 tw[512];
    __shared__ float2 bufA[1024];
    __shared__ float2 bufB[1024];
    __shared__ float  red[16];

    {
        float s_, c_;
        sincospif((float)t * (1.0f/512.0f), &s_, &c_);
        tw[t] = make_float2(c_, -s_);
    }

    {   // build conj(mixF) full spectrum (for ifft-via-fft trick)
        float2 kx = g_kx[(size_t)row*NF + t];
        float2 sf = g_sf[b*NF + t];
        float2 qf = g_qf[(size_t)row*NF + t];
        float2 qc = make_float2(qf.x, -qf.y);
        float2 p  = cmulf(sf, qc);
        float2 mv = make_float2(kx.x + p.x, kx.y + p.y);
        bufA[t] = make_float2(mv.x, -mv.y);
        if (t > 0) bufA[1024 - t] = mv;  // conj(mixF[N-t]) = mixF[t]
        if (t == 0) {
            float2 kx5 = g_kx[(size_t)row*NF + 512];
            float2 sf5 = g_sf[b*NF + 512];
            float2 qf5 = g_qf[(size_t)row*NF + 512];
            float2 qc5 = make_float2(qf5.x, -qf5.y);
            float2 p5  = cmulf(sf5, qc5);
            bufA[512] = make_float2(kx5.x + p5.x, -(kx5.y + p5.y));
        }
    }
    __syncthreads();
    float2* R = fft1024(bufA, bufB, tw, t);

    const float invN = 1.0f / 1024.0f;
    const float* xr = x + (size_t)row * DIMS;
    float y0 = xr[t]     + R[t].x     * invN;
    float y1 = xr[t+512] + R[t+512].x * invN;

    float s  = block_sum512(y0 + y1, red);
    float ss = block_sum512(y0*y0 + y1*y1, red);
    float m = s * invN, v = ss * invN - m*m;
    float r = rsqrtf(v + 1e-5f);
    float* o = g_x1 + (size_t)row * DIMS;
    o[t]     = (y0 - m) * r * g0[t]     + beta0[t];
    o[t+512] = (y1 - m) * r * g0[t+512] + beta0[t+512];
}

// ---------------- out = LN(x1 + ff) ----------------
__global__ void __launch_bounds__(512) resid_ln_kernel(
    const float* __restrict__ g1v, const float* __restrict__ beta1,
    float* __restrict__ out)
{
    const int row = blockIdx.x;
    const int t = threadIdx.x;
    __shared__ float red[16];
    const float* a = g_x1 + (size_t)row * DIMS;
    const float* f = g_ff + (size_t)row * DIMS;
    float y0 = a[t]     + f[t];
    float y1 = a[t+512] + f[t+512];
    const float invN = 1.0f / 1024.0f;
    float s  = block_sum512(y0 + y1, red);
    float ss = block_sum512(y0*y0 + y1*y1, red);
    float m = s * invN, v = ss * invN - m*m;
    float r = rsqrtf(v + 1e-5f);
    float* o = out + (size_t)row * DIMS;
    o[t]     = (y0 - m) * r * g1v[t]     + beta1[t];
    o[t+512] = (y1 - m) * r * g1v[t+512] + beta1[t+512];
}

// ---------------- launch ----------------
extern "C" void kernel_launch(void* const* d_in, const int* in_sizes, int n_in,
                              void* d_out, int out_size)
{
    const float* x     = (const float*)d_in[0];
    const float* Wq    = (const float*)d_in[1];
    const float* bq    = (const float*)d_in[2];
    const float* gq    = (const float*)d_in[3];
    const float* betaq = (const float*)d_in[4];
    const float* Wk    = (const float*)d_in[5];
    const float* bk    = (const float*)d_in[6];
    const float* gk    = (const float*)d_in[7];
    const float* betak = (const float*)d_in[8];
    const float* g0    = (const float*)d_in[9];
    const float* beta0 = (const float*)d_in[10];
    const float* W1    = (const float*)d_in[11];
    const float* b1    = (const float*)d_in[12];
    const float* W2    = (const float*)d_in[13];
    const float* b2    = (const float*)d_in[14];
    const float* g1    = (const float*)d_in[15];
    const float* beta1 = (const float*)d_in[16];
    float* out = (float*)d_out;

    float *pq, *pk, *px1, *ph, *pff;
    cudaGetSymbolAddress((void**)&pq,  g_q);
    cudaGetSymbolAddress((void**)&pk,  g_k);
    cudaGetSymbolAddress((void**)&px1, g_x1);
    cudaGetSymbolAddress((void**)&ph,  g_h);
    cudaGetSymbolAddress((void**)&pff, g_ff);

    // q_raw = x @ Wq^T + bq ; k_raw = x @ Wk^T + bk
    gemm_nt<0><<<dim3(DIMS/128, ROWS/128), 256>>>(x, Wq, bq, pq, ROWS, DIMS, DIMS);
    gemm_nt<0><<<dim3(DIMS/128, ROWS/128), 256>>>(x, Wk, bk, pk, ROWS, DIMS, DIMS);
    // LN(q), LN(k), forward FFTs, Kx, Qf
    fft_fwd_kernel<<<ROWS, 512>>>(x, gq, betaq, gk, betak);
    // S = sum_s Kx (freq domain)
    reduce_s_kernel<<<dim3(BATCH, NF), 256>>>();
    // mix = irfft(Kx + S*conj(Qf)); x1 = LN(x + mix)
    fft_inv_ln_kernel<<<ROWS, 512>>>(x, g0, beta0);
    // h = relu(x1 @ W1^T + b1)
    gemm_nt<1><<<dim3(FFD/128, ROWS/128), 256>>>(px1, W1, b1, ph, ROWS, FFD, DIMS);
    // ff = h @ W2^T + b2
    gemm_nt<0><<<dim3(DIMS/128, ROWS/128), 256>>>(ph, W2, b2, pff, ROWS, DIMS, FFD);
    // out = LN(x1 + ff)
    resid_ln_kernel<<<ROWS, 512>>>(g1, beta1, out);
}

// round 3
// speedup vs baseline: 2.1312x; 2.1312x over previous
#include <cuda_runtime.h>
#include <math.h>
#include <stdint.h>

#define DIMS 1024
#define FFD  4096
#define BATCH 4
#define SEQ  4096
#define ROWS (BATCH*SEQ)   // 16384
#define NF   513           // rfft bins for N=1024

// ---------------- scratch (device globals; no allocation allowed) ----------------
__device__ float  g_q [(size_t)ROWS*DIMS];
__device__ float  g_k [(size_t)ROWS*DIMS];
__device__ float  g_x1[(size_t)ROWS*DIMS];
__device__ float  g_ff[(size_t)ROWS*DIMS];
__device__ float  g_h [(size_t)ROWS*FFD];
__device__ float2 g_kx[(size_t)ROWS*NF];
__device__ float2 g_qf[(size_t)ROWS*NF];
__device__ float2 g_sf[BATCH*NF];

// ---------------- PTX helpers ----------------
__device__ __forceinline__ uint32_t smem_u32(const void* p) {
    uint32_t a;
    asm("{ .reg .u64 t; cvta.to.shared.u64 t, %1; cvt.u32.u64 %0, t; }" : "=r"(a) : "l"(p));
    return a;
}
__device__ __forceinline__ void cp16(uint32_t dst, const void* src) {
    asm volatile("cp.async.cg.shared.global [%0], [%1], 16;" :: "r"(dst), "l"(src));
}
#define CP_COMMIT() asm volatile("cp.async.commit_group;" ::: "memory")
template<int N> __device__ __forceinline__ void cp_wait() {
    asm volatile("cp.async.wait_group %0;" :: "n"(N) : "memory");
}
__device__ __forceinline__ uint32_t f2tf32(float v) {
    uint32_t u;
    asm("cvt.rna.tf32.f32 %0, %1;" : "=r"(u) : "f"(v));
    return u;
}
__device__ __forceinline__ void mma_tf32(float& c0, float& c1, float& c2, float& c3,
                                         uint32_t a0, uint32_t a1, uint32_t a2, uint32_t a3,
                                         uint32_t b0, uint32_t b1) {
    asm volatile(
        "mma.sync.aligned.m16n8k8.row.col.f32.tf32.tf32.f32 "
        "{%0,%1,%2,%3}, {%4,%5,%6,%7}, {%8,%9}, {%0,%1,%2,%3};"
        : "+f"(c0), "+f"(c1), "+f"(c2), "+f"(c3)
        : "r"(a0), "r"(a1), "r"(a2), "r"(a3), "r"(b0), "r"(b1));
}

// ======================= mma.sync tf32 GEMM =======================
// C[M,N] = A[M,K] * B[N,K]^T + bias (both row-major, K contiguous).
// 128x128x32 CTA tile, 256 threads (8 warps = 2Mx4N, warp tile 64x32),
// 3-stage cp.async pipeline, padded shared (stride 36 floats).
#define BK 32
#define LDT 36            // padded floats per row in shared
#define TILE_FLOATS (128*LDT)
#define STAGE_FLOATS (2*TILE_FLOATS)
#define NSTAGE 3

template<int RELU>
__global__ void __launch_bounds__(256)
gemm_mma(const float* __restrict__ A, const float* __restrict__ B,
         const float* __restrict__ bias, float* __restrict__ C,
         int N, int K)
{
    extern __shared__ float smem[];
    const int tid = threadIdx.x;
    const int warp = tid >> 5;
    const int lane = tid & 31;
    const int wm = warp & 1;          // 0..1  (M)
    const int wn = warp >> 1;         // 0..3  (N)
    const int lr = lane >> 2;         // 0..7
    const int lc = lane & 3;          // 0..3

    const float* Ab = A + (size_t)blockIdx.y * 128 * K;
    const float* Bb = B + (size_t)blockIdx.x * 128 * K;

    const uint32_t sbase = smem_u32(smem);
    const int row = tid >> 1;          // 0..127
    const int half = tid & 1;          // 0..1

    const int ktiles = K / BK;

    auto load_stage = [&](int stage, int kt) {
        const int k0 = kt * BK;
        const uint32_t sA = sbase + stage * (STAGE_FLOATS * 4);
        const uint32_t sB = sA + TILE_FLOATS * 4;
        const float* ga = Ab + (size_t)row * K + k0 + half * 16;
        const float* gb = Bb + (size_t)row * K + k0 + half * 16;
        const uint32_t so = (uint32_t)(row * LDT + half * 16) * 4;
        #pragma unroll
        for (int c = 0; c < 4; c++) {
            cp16(sA + so + c * 16, ga + c * 4);
            cp16(sB + so + c * 16, gb + c * 4);
        }
    };

    // prologue
    load_stage(0, 0); CP_COMMIT();
    load_stage(1, 1); CP_COMMIT();

    float acc[4][4][4];
    #pragma unroll
    for (int i = 0; i < 4; i++)
        #pragma unroll
        for (int j = 0; j < 4; j++)
            #pragma unroll
            for (int r = 0; r < 4; r++) acc[i][j][r] = 0.f;

    for (int it = 0; it < ktiles; it++) {
        cp_wait<1>();
        __syncthreads();

        const float* sA = smem + (it % NSTAGE) * STAGE_FLOATS;
        const float* sB = sA + TILE_FLOATS;

        // issue next loads first (overlap with compute)
        const int nt = it + 2;
        if (nt < ktiles) load_stage(nt % NSTAGE, nt);
        CP_COMMIT();

        #pragma unroll
        for (int ks = 0; ks < 4; ks++) {
            const int kb = ks * 8;
            uint32_t a[4][4], b[4][2];
            #pragma unroll
            for (int mt = 0; mt < 4; mt++) {
                const int r0 = wm * 64 + mt * 16 + lr;
                const float* p = sA + r0 * LDT + kb + lc;
                a[mt][0] = f2tf32(p[0]);
                a[mt][1] = f2tf32(p[8 * LDT]);
                a[mt][2] = f2tf32(p[4]);
                a[mt][3] = f2tf32(p[8 * LDT + 4]);
            }
            #pragma unroll
            for (int ntc = 0; ntc < 4; ntc++) {
                const int n0 = wn * 32 + ntc * 8 + lr;
                const float* p = sB + n0 * LDT + kb + lc;
                b[ntc][0] = f2tf32(p[0]);
                b[ntc][1] = f2tf32(p[4]);
            }
            #pragma unroll
            for (int mt = 0; mt < 4; mt++)
                #pragma unroll
                for (int ntc = 0; ntc < 4; ntc++)
                    mma_tf32(acc[mt][ntc][0], acc[mt][ntc][1],
                             acc[mt][ntc][2], acc[mt][ntc][3],
                             a[mt][0], a[mt][1], a[mt][2], a[mt][3],
                             b[ntc][0], b[ntc][1]);
        }
        __syncthreads();
    }

    // epilogue
    const int crow0 = blockIdx.y * 128 + wm * 64;
    const int ccol0 = blockIdx.x * 128 + wn * 32;
    #pragma unroll
    for (int mt = 0; mt < 4; mt++) {
        #pragma unroll
        for (int ntc = 0; ntc < 4; ntc++) {
            const int r0 = crow0 + mt * 16 + lr;
            const int c0 = ccol0 + ntc * 8 + lc * 2;
            float b0 = __ldg(bias + c0);
            float b1 = __ldg(bias + c0 + 1);
            float v0 = acc[mt][ntc][0] + b0;
            float v1 = acc[mt][ntc][1] + b1;
            float v2 = acc[mt][ntc][2] + b0;
            float v3 = acc[mt][ntc][3] + b1;
            if (RELU) {
                v0 = fmaxf(v0, 0.f); v1 = fmaxf(v1, 0.f);
                v2 = fmaxf(v2, 0.f); v3 = fmaxf(v3, 0.f);
            }
            *(float2*)(C + (size_t)r0 * N + c0)       = make_float2(v0, v1);
            *(float2*)(C + (size_t)(r0 + 8) * N + c0) = make_float2(v2, v3);
        }
    }
}

// ---------------- helpers for FFT path ----------------
__device__ __forceinline__ float2 cmulf(float2 a, float2 b) {
    return make_float2(a.x*b.x - a.y*b.y, a.x*b.y + a.y*b.x);
}

__device__ __forceinline__ float block_sum512(float v, volatile float* red) {
    int t = threadIdx.x;
    #pragma unroll
    for (int o = 16; o; o >>= 1) v += __shfl_xor_sync(0xffffffffu, v, o);
    if ((t & 31) == 0) red[t >> 5] = v;
    __syncthreads();
    if (t == 0) {
        float s = 0.f;
        #pragma unroll
        for (int i = 0; i < 16; i++) s += red[i];
        red[0] = s;
    }
    __syncthreads();
    float r = red[0];
    __syncthreads();
    return r;
}

__device__ __forceinline__ float2* fft1024(float2* bufA, float2* bufB,
                                           const float2* tw, int t) {
    float2* src = bufA; float2* dst = bufB;
    #pragma unroll
    for (int m = 1; m <= 512; m <<= 1) {
        float2 a = src[t];
        float2 b = src[t + 512];
        int jm = t & ~(m - 1);
        float2 w = tw[jm];
        float2 s = make_float2(a.x + b.x, a.y + b.y);
        float2 d = make_float2(a.x - b.x, a.y - b.y);
        float2 r = make_float2(d.x*w.x - d.y*w.y, d.x*w.y + d.y*w.x);
        dst[t + jm]     = s;
        dst[t + jm + m] = r;
        __syncthreads();
        float2* tmp = src; src = dst; dst = tmp;
    }
    return src;
}

// ---------------- forward FFTs: LN(q), LN(k); Kx = Xf*Kf; Qf ----------------
__global__ void __launch_bounds__(512) fft_fwd_kernel(
    const float* __restrict__ x,
    const float* __restrict__ gq, const float* __restrict__ betaq,
    const float* __restrict__ gk, const float* __restrict__ betak)
{
    const int row = blockIdx.x;
    const int t = threadIdx.x;
    __shared__ float2 tw[512];
    __shared__ float2 bufA[1024];
    __shared__ float2 bufB[1024];
    __shared__ float  red[16];

    {
        float s_, c_;
        sincospif((float)t * (1.0f/512.0f), &s_, &c_);
        tw[t] = make_float2(c_, -s_);
    }

    const float* xr = x   + (size_t)row * DIMS;
    const float* qr = g_q + (size_t)row * DIMS;
    const float* kr = g_k + (size_t)row * DIMS;
    float x0 = xr[t], x1 = xr[t+512];
    float q0 = qr[t], q1 = qr[t+512];
    float k0 = kr[t], k1 = kr[t+512];

    const float invN = 1.0f / 1024.0f;
    float qs  = block_sum512(q0 + q1, red);
    float qss = block_sum512(q0*q0 + q1*q1, red);
    float ks  = block_sum512(k0 + k1, red);
    float kss = block_sum512(k0*k0 + k1*k1, red);
    float mq = qs * invN, vq = qss * invN - mq*mq;
    float rq = rsqrtf(vq + 1e-5f);
    float mk = ks * invN, vk = kss * invN - mk*mk;
    float rk = rsqrtf(vk + 1e-5f);
    float qn0 = (q0 - mq) * rq * gq[t]     + betaq[t];
    float qn1 = (q1 - mq) * rq * gq[t+512] + betaq[t+512];
    float kn0 = (k0 - mk) * rk * gk[t]     + betak[t];
    float kn1 = (k1 - mk) * rk * gk[t+512] + betak[t+512];

    bufA[t]     = make_float2(x0, kn0);
    bufA[t+512] = make_float2(x1, kn1);
    __syncthreads();
    float2* Z = fft1024(bufA, bufB, tw, t);

    {
        float2 z  = Z[t];
        float2 zn = Z[(1024 - t) & 1023];
        float2 xf = make_float2(0.5f*(z.x + zn.x), 0.5f*(z.y - zn.y));
        float2 df = make_float2(z.x - zn.x, z.y + zn.y);
        float2 kf = make_float2(0.5f*df.y, -0.5f*df.x);
        g_kx[(size_t)row*NF + t] = cmulf(xf, kf);
        if (t == 0) {
            float2 z5 = Z[512];
            g_kx[(size_t)row*NF + 512] = make_float2(z5.x * z5.y, 0.f);
        }
    }
    __syncthreads();

    bufA[t]     = make_float2(qn0, 0.f);
    bufA[t+512] = make_float2(qn1, 0.f);
    __syncthreads();
    float2* Q = fft1024(bufA, bufB, tw, t);
    g_qf[(size_t)row*NF + t] = Q[t];
    if (t == 0) g_qf[(size_t)row*NF + 512] = Q[512];
}

// ---------------- reduce S_freq[b] = sum_s Kx[b,s] ----------------
__global__ void __launch_bounds__(256) reduce_s_kernel() {
    const int b = blockIdx.x;
    const int j = blockIdx.y;
    const int t = threadIdx.x;
    float2 acc = make_float2(0.f, 0.f);
    const float2* p = g_kx + (size_t)b * SEQ * NF + j;
    for (int s = t; s < SEQ; s += 256) {
        float2 v = p[(size_t)s * NF];
        acc.x += v.x; acc.y += v.y;
    }
    __shared__ float2 red[256];
    red[t] = acc;
    __syncthreads();
    for (int o = 128; o; o >>= 1) {
        if (t < o) { red[t].x += red[t+o].x; red[t].y += red[t+o].y; }
        __syncthreads();
    }
    if (t == 0) g_sf[b * NF + j] = red[0];
}

// ---------------- inverse FFT of mixF = Kx + S*conj(Qf); LN(x + mix) ----------------
__global__ void __launch_bounds__(512) fft_inv_ln_kernel(
    const float* __restrict__ x,
    const float* __restrict__ g0, const float* __restrict__ beta0)
{
    const int row = blockIdx.x;
    const int b = row >> 12;
    const int t = threadIdx.x;
    __shared__ float2 tw[512];
    __shared__ float2 bufA[1024];
    __shared__ float2 bufB[1024];
    __shared__ float  red[16];

    {
        float s_, c_;
        sincospif((float)t * (1.0f/512.0f), &s_, &c_);
        tw[t] = make_float2(c_, -s_);
    }

    {
        float2 kx = g_kx[(size_t)row*NF + t];
        float2 sf = g_sf[b*NF + t];
        float2 qf = g_qf[(size_t)row*NF + t];
        float2 qc = make_float2(qf.x, -qf.y);
        float2 p  = cmulf(sf, qc);
        float2 mv = make_float2(kx.x + p.x, kx.y + p.y);
        bufA[t] = make_float2(mv.x, -mv.y);
        if (t > 0) bufA[1024 - t] = mv;
        if (t == 0) {
            float2 kx5 = g_kx[(size_t)row*NF + 512];
            float2 sf5 = g_sf[b*NF + 512];
            float2 qf5 = g_qf[(size_t)row*NF + 512];
            float2 qc5 = make_float2(qf5.x, -qf5.y);
            float2 p5  = cmulf(sf5, qc5);
            bufA[512] = make_float2(kx5.x + p5.x, -(kx5.y + p5.y));
        }
    }
    __syncthreads();
    float2* R = fft1024(bufA, bufB, tw, t);

    const float invN = 1.0f / 1024.0f;
    const float* xr = x + (size_t)row * DIMS;
    float y0 = xr[t]     + R[t].x     * invN;
    float y1 = xr[t+512] + R[t+512].x * invN;

    float s  = block_sum512(y0 + y1, red);
    float ss = block_sum512(y0*y0 + y1*y1, red);
    float m = s * invN, v = ss * invN - m*m;
    float r = rsqrtf(v + 1e-5f);
    float* o = g_x1 + (size_t)row * DIMS;
    o[t]     = (y0 - m) * r * g0[t]     + beta0[t];
    o[t+512] = (y1 - m) * r * g0[t+512] + beta0[t+512];
}

// ---------------- out = LN(x1 + ff) ----------------
__global__ void __launch_bounds__(512) resid_ln_kernel(
    const float* __restrict__ g1v, const float* __restrict__ beta1,
    float* __restrict__ out)
{
    const int row = blockIdx.x;
    const int t = threadIdx.x;
    __shared__ float red[16];
    const float* a = g_x1 + (size_t)row * DIMS;
    const float* f = g_ff + (size_t)row * DIMS;
    float y0 = a[t]     + f[t];
    float y1 = a[t+512] + f[t+512];
    const float invN = 1.0f / 1024.0f;
    float s  = block_sum512(y0 + y1, red);
    float ss = block_sum512(y0*y0 + y1*y1, red);
    float m = s * invN, v = ss * invN - m*m;
    float r = rsqrtf(v + 1e-5f);
    float* o = out + (size_t)row * DIMS;
    o[t]     = (y0 - m) * r * g1v[t]     + beta1[t];
    o[t+512] = (y1 - m) * r * g1v[t+512] + beta1[t+512];
}

// ---------------- launch ----------------
extern "C" void kernel_launch(void* const* d_in, const int* in_sizes, int n_in,
                              void* d_out, int out_size)
{
    const float* x     = (const float*)d_in[0];
    const float* Wq    = (const float*)d_in[1];
    const float* bq    = (const float*)d_in[2];
    const float* gq    = (const float*)d_in[3];
    const float* betaq = (const float*)d_in[4];
    const float* Wk    = (const float*)d_in[5];
    const float* bk    = (const float*)d_in[6];
    const float* gk    = (const float*)d_in[7];
    const float* betak = (const float*)d_in[8];
    const float* g0    = (const float*)d_in[9];
    const float* beta0 = (const float*)d_in[10];
    const float* W1    = (const float*)d_in[11];
    const float* b1    = (const float*)d_in[12];
    const float* W2    = (const float*)d_in[13];
    const float* b2    = (const float*)d_in[14];
    const float* g1    = (const float*)d_in[15];
    const float* beta1 = (const float*)d_in[16];
    float* out = (float*)d_out;

    float *pq, *pk, *px1, *ph, *pff;
    cudaGetSymbolAddress((void**)&pq,  g_q);
    cudaGetSymbolAddress((void**)&pk,  g_k);
    cudaGetSymbolAddress((void**)&px1, g_x1);
    cudaGetSymbolAddress((void**)&ph,  g_h);
    cudaGetSymbolAddress((void**)&pff, g_ff);

    const int SMEM = NSTAGE * STAGE_FLOATS * 4;  // 3*2*128*36*4 = 110592 B
    cudaFuncSetAttribute(gemm_mma<0>, cudaFuncAttributeMaxDynamicSharedMemorySize, SMEM);
    cudaFuncSetAttribute(gemm_mma<1>, cudaFuncAttributeMaxDynamicSharedMemorySize, SMEM);

    // q_raw = x @ Wq^T + bq ; k_raw = x @ Wk^T + bk   (tf32 mma.sync)
    gemm_mma<0><<<dim3(DIMS/128, ROWS/128), 256, SMEM>>>(x, Wq, bq, pq, DIMS, DIMS);
    gemm_mma<0><<<dim3(DIMS/128, ROWS/128), 256, SMEM>>>(x, Wk, bk, pk, DIMS, DIMS);
    // LN(q), LN(k), forward FFTs, Kx, Qf
    fft_fwd_kernel<<<ROWS, 512>>>(x, gq, betaq, gk, betak);
    // S = sum_s Kx (freq domain)
    reduce_s_kernel<<<dim3(BATCH, NF), 256>>>();
    // mix = irfft(Kx + S*conj(Qf)); x1 = LN(x + mix)
    fft_inv_ln_kernel<<<ROWS, 512>>>(x, g0, beta0);
    // h = relu(x1 @ W1^T + b1)
    gemm_mma<1><<<dim3(FFD/128, ROWS/128), 256, SMEM>>>(px1, W1, b1, ph, FFD, DIMS);
    // ff = h @ W2^T + b2
    gemm_mma<0><<<dim3(DIMS/128, ROWS/128), 256, SMEM>>>(ph, W2, b2, pff, DIMS, FFD);
    // out = LN(x1 + ff)
    resid_ln_kernel<<<ROWS, 512>>>(g1, beta1, out);
}

// round 4
// speedup vs baseline: 2.2093x; 1.0366x over previous
#include <cuda_runtime.h>
#include <math.h>
#include <stdint.h>

#define DIMS 1024
#define FFD  4096
#define BATCH 4
#define SEQ  4096
#define ROWS (BATCH*SEQ)   // 16384
#define NF   513           // rfft bins for N=1024

// ---------------- scratch (device globals; no allocation allowed) ----------------
__device__ float  g_qk [(size_t)ROWS*2*DIMS];   // q | k packed per row (N=2048 GEMM out)
__device__ float  g_x1 [(size_t)ROWS*DIMS];     // full-precision LN output (residual)
__device__ float  g_x1r[(size_t)ROWS*DIMS];     // tf32-rounded copy (GEMM input)
__device__ float  g_ff [(size_t)ROWS*DIMS];
__device__ float  g_h  [(size_t)ROWS*FFD];      // rounded at write
__device__ float  g_xr [(size_t)ROWS*DIMS];     // tf32-rounded x
__device__ float  g_wr [(size_t)(2*DIMS*DIMS + 2*DIMS*FFD)]; // Wqk | W1 | W2 rounded
__device__ float  g_br [2*DIMS];                // bq | bk packed
__device__ float2 g_kx[(size_t)ROWS*NF];
__device__ float2 g_qf[(size_t)ROWS*NF];
__device__ float2 g_sf[BATCH*NF];

#define WQK_OFF 0
#define W1_OFF  (2*DIMS*DIMS)
#define W2_OFF  (2*DIMS*DIMS + DIMS*FFD)

// ---------------- PTX helpers ----------------
__device__ __forceinline__ uint32_t smem_u32(const void* p) {
    uint32_t a;
    asm("{ .reg .u64 t; cvta.to.shared.u64 t, %1; cvt.u32.u64 %0, t; }" : "=r"(a) : "l"(p));
    return a;
}
__device__ __forceinline__ void cp16(uint32_t dst, const void* src) {
    asm volatile("cp.async.cg.shared.global [%0], [%1], 16;" :: "r"(dst), "l"(src));
}
#define CP_COMMIT() asm volatile("cp.async.commit_group;" ::: "memory")
template<int N> __device__ __forceinline__ void cp_wait() {
    asm volatile("cp.async.wait_group %0;" :: "n"(N) : "memory");
}
__device__ __forceinline__ float f2tf32f(float v) {
    uint32_t u;
    asm("cvt.rna.tf32.f32 %0, %1;" : "=r"(u) : "f"(v));
    return __uint_as_float(u);
}
__device__ __forceinline__ void mma_tf32(float& c0, float& c1, float& c2, float& c3,
                                         uint32_t a0, uint32_t a1, uint32_t a2, uint32_t a3,
                                         uint32_t b0, uint32_t b1) {
    asm volatile(
        "mma.sync.aligned.m16n8k8.row.col.f32.tf32.tf32.f32 "
        "{%0,%1,%2,%3}, {%4,%5,%6,%7}, {%8,%9}, {%0,%1,%2,%3};"
        : "+f"(c0), "+f"(c1), "+f"(c2), "+f"(c3)
        : "r"(a0), "r"(a1), "r"(a2), "r"(a3), "r"(b0), "r"(b1));
}
__device__ __forceinline__ void ldsm_x4(uint32_t& r0, uint32_t& r1, uint32_t& r2, uint32_t& r3,
                                        uint32_t addr) {
    asm volatile("ldmatrix.sync.aligned.m8n8.x4.shared.b16 {%0,%1,%2,%3}, [%4];"
                 : "=r"(r0), "=r"(r1), "=r"(r2), "=r"(r3) : "r"(addr));
}
__device__ __forceinline__ void ldsm_x2(uint32_t& r0, uint32_t& r1, uint32_t addr) {
    asm volatile("ldmatrix.sync.aligned.m8n8.x2.shared.b16 {%0,%1}, [%2];"
                 : "=r"(r0), "=r"(r1) : "r"(addr));
}

// ---------------- tf32 rounding pre-passes ----------------
__global__ void __launch_bounds__(256) round_kernel(const float* __restrict__ src,
                                                    float* __restrict__ dst, int n4) {
    int i = blockIdx.x * 256 + threadIdx.x;
    if (i < n4) {
        float4 v = ((const float4*)src)[i];
        v.x = f2tf32f(v.x); v.y = f2tf32f(v.y);
        v.z = f2tf32f(v.z); v.w = f2tf32f(v.w);
        ((float4*)dst)[i] = v;
    }
}
__global__ void pack_bias_kernel(const float* __restrict__ bq, const float* __restrict__ bk) {
    int i = blockIdx.x * 256 + threadIdx.x;
    if (i < DIMS) { g_br[i] = bq[i]; g_br[i + DIMS] = bk[i]; }
}

// ======================= mma.sync tf32 GEMM (ldmatrix, pre-rounded) =======================
// C[M,N] = A[M,K] * B[N,K]^T + bias. 128x128x32 CTA tile, 256 threads (8 warps 2Mx4N),
// warp tile 64x32, 3-stage cp.async pipeline, padded shared stride 36 floats.
#define BK 32
#define LDT 36
#define TILE_FLOATS (128*LDT)
#define STAGE_FLOATS (2*TILE_FLOATS)
#define NSTAGE 3

template<int RELU, int ROUND>
__global__ void __launch_bounds__(256)
gemm_mma(const float* __restrict__ A, const float* __restrict__ B,
         const float* __restrict__ bias, float* __restrict__ C,
         int N, int K)
{
    extern __shared__ float smem[];
    const int tid = threadIdx.x;
    const int warp = tid >> 5;
    const int lane = tid & 31;
    const int wm = warp & 1;
    const int wn = warp >> 1;
    const int lr = lane >> 2;
    const int lc = lane & 3;

    const float* Ab = A + (size_t)blockIdx.y * 128 * K;
    const float* Bb = B + (size_t)blockIdx.x * 128 * K;

    const uint32_t sbase = smem_u32(smem);
    const int row = tid >> 1;
    const int half = tid & 1;
    const int ktiles = K / BK;

    // ldmatrix per-lane base offsets (bytes), relative to tile start
    //   A (x4): m0 rows r0..r0+7 bytes[0:16), m1 rows +8, m2 bytes[16:32), m3 rows+8 b[16:32)
    uint32_t aoff[4];
    {
        const int l7 = lane & 7;
        const int rsel = (lane >> 3) & 1;   // +8 rows for m1/m3
        const int csel = (lane >> 4);       // +4 floats for m2/m3
        #pragma unroll
        for (int mt = 0; mt < 4; mt++) {
            int r = wm * 64 + mt * 16 + l7 + rsel * 8;
            aoff[mt] = (uint32_t)(r * LDT + csel * 4) * 4u;
        }
    }
    //   B (x2): m0 rows n0..n0+7 bytes[0:16) -> b0 ; m1 same rows bytes[16:32) -> b1
    uint32_t boff[4];
    {
        const int l15 = lane & 15;
        const int l7 = l15 & 7;
        const int csel = (l15 >> 3) & 1;
        #pragma unroll
        for (int nt = 0; nt < 4; nt++) {
            int r = wn * 32 + nt * 8 + l7;
            boff[nt] = (uint32_t)(r * LDT + csel * 4) * 4u;
        }
    }

    auto load_stage = [&](int stage, int kt) {
        const int k0 = kt * BK;
        const uint32_t sA = sbase + stage * (STAGE_FLOATS * 4);
        const uint32_t sB = sA + TILE_FLOATS * 4;
        const float* ga = Ab + (size_t)row * K + k0 + half * 16;
        const float* gb = Bb + (size_t)row * K + k0 + half * 16;
        const uint32_t so = (uint32_t)(row * LDT + half * 16) * 4;
        #pragma unroll
        for (int c = 0; c < 4; c++) {
            cp16(sA + so + c * 16, ga + c * 4);
            cp16(sB + so + c * 16, gb + c * 4);
        }
    };

    load_stage(0, 0); CP_COMMIT();
    load_stage(1, 1); CP_COMMIT();

    float acc[4][4][4];
    #pragma unroll
    for (int i = 0; i < 4; i++)
        #pragma unroll
        for (int j = 0; j < 4; j++)
            #pragma unroll
            for (int r = 0; r < 4; r++) acc[i][j][r] = 0.f;

    for (int it = 0; it < ktiles; it++) {
        cp_wait<1>();
        __syncthreads();

        const uint32_t sA = sbase + (it % NSTAGE) * (STAGE_FLOATS * 4);
        const uint32_t sB = sA + TILE_FLOATS * 4;

        const int nt2 = it + 2;
        if (nt2 < ktiles) load_stage(nt2 % NSTAGE, nt2);
        CP_COMMIT();

        #pragma unroll
        for (int ks = 0; ks < 4; ks++) {
            const uint32_t kboff = ks * 32;  // 8 floats
            uint32_t a[4][4], b[4][2];
            #pragma unroll
            for (int mt = 0; mt < 4; mt++)
                ldsm_x4(a[mt][0], a[mt][1], a[mt][2], a[mt][3], sA + aoff[mt] + kboff);
            #pragma unroll
            for (int nt = 0; nt < 4; nt++)
                ldsm_x2(b[nt][0], b[nt][1], sB + boff[nt] + kboff);
            #pragma unroll
            for (int mt = 0; mt < 4; mt++)
                #pragma unroll
                for (int nt = 0; nt < 4; nt++)
                    mma_tf32(acc[mt][nt][0], acc[mt][nt][1],
                             acc[mt][nt][2], acc[mt][nt][3],
                             a[mt][0], a[mt][1], a[mt][2], a[mt][3],
                             b[nt][0], b[nt][1]);
        }
        __syncthreads();
    }

    // epilogue
    const int crow0 = blockIdx.y * 128 + wm * 64;
    const int ccol0 = blockIdx.x * 128 + wn * 32;
    #pragma unroll
    for (int mt = 0; mt < 4; mt++) {
        #pragma unroll
        for (int nt = 0; nt < 4; nt++) {
            const int r0 = crow0 + mt * 16 + lr;
            const int c0 = ccol0 + nt * 8 + lc * 2;
            float b0 = __ldg(bias + c0);
            float b1 = __ldg(bias + c0 + 1);
            float v0 = acc[mt][nt][0] + b0;
            float v1 = acc[mt][nt][1] + b1;
            float v2 = acc[mt][nt][2] + b0;
            float v3 = acc[mt][nt][3] + b1;
            if (RELU) {
                v0 = fmaxf(v0, 0.f); v1 = fmaxf(v1, 0.f);
                v2 = fmaxf(v2, 0.f); v3 = fmaxf(v3, 0.f);
            }
            if (ROUND) {
                v0 = f2tf32f(v0); v1 = f2tf32f(v1);
                v2 = f2tf32f(v2); v3 = f2tf32f(v3);
            }
            *(float2*)(C + (size_t)r0 * N + c0)       = make_float2(v0, v1);
            *(float2*)(C + (size_t)(r0 + 8) * N + c0) = make_float2(v2, v3);
        }
    }
}

// ---------------- helpers for FFT path ----------------
__device__ __forceinline__ float2 cmulf(float2 a, float2 b) {
    return make_float2(a.x*b.x - a.y*b.y, a.x*b.y + a.y*b.x);
}

__device__ __forceinline__ float block_sum512(float v, volatile float* red) {
    int t = threadIdx.x;
    #pragma unroll
    for (int o = 16; o; o >>= 1) v += __shfl_xor_sync(0xffffffffu, v, o);
    if ((t & 31) == 0) red[t >> 5] = v;
    __syncthreads();
    if (t == 0) {
        float s = 0.f;
        #pragma unroll
        for (int i = 0; i < 16; i++) s += red[i];
        red[0] = s;
    }
    __syncthreads();
    float r = red[0];
    __syncthreads();
    return r;
}

__device__ __forceinline__ float2* fft1024(float2* bufA, float2* bufB,
                                           const float2* tw, int t) {
    float2* src = bufA; float2* dst = bufB;
    #pragma unroll
    for (int m = 1; m <= 512; m <<= 1) {
        float2 a = src[t];
        float2 b = src[t + 512];
        int jm = t & ~(m - 1);
        float2 w = tw[jm];
        float2 s = make_float2(a.x + b.x, a.y + b.y);
        float2 d = make_float2(a.x - b.x, a.y - b.y);
        float2 r = make_float2(d.x*w.x - d.y*w.y, d.x*w.y + d.y*w.x);
        dst[t + jm]     = s;
        dst[t + jm + m] = r;
        __syncthreads();
        float2* tmp = src; src = dst; dst = tmp;
    }
    return src;
}

// ---------------- forward FFTs: LN(q), LN(k); Kx = Xf*Kf; Qf ----------------
__global__ void __launch_bounds__(512) fft_fwd_kernel(
    const float* __restrict__ x,
    const float* __restrict__ gq, const float* __restrict__ betaq,
    const float* __restrict__ gk, const float* __restrict__ betak)
{
    const int row = blockIdx.x;
    const int t = threadIdx.x;
    __shared__ float2 tw[512];
    __shared__ float2 bufA[1024];
    __shared__ float2 bufB[1024];
    __shared__ float  red[16];

    {
        float s_, c_;
        sincospif((float)t * (1.0f/512.0f), &s_, &c_);
        tw[t] = make_float2(c_, -s_);
    }

    const float* xr = x    + (size_t)row * DIMS;
    const float* qr = g_qk + (size_t)row * 2 * DIMS;
    const float* kr = qr + DIMS;
    float x0 = xr[t], x1 = xr[t+512];
    float q0 = qr[t], q1 = qr[t+512];
    float k0 = kr[t], k1 = kr[t+512];

    const float invN = 1.0f / 1024.0f;
    float qs  = block_sum512(q0 + q1, red);
    float qss = block_sum512(q0*q0 + q1*q1, red);
    float ks  = block_sum512(k0 + k1, red);
    float kss = block_sum512(k0*k0 + k1*k1, red);
    float mq = qs * invN, vq = qss * invN - mq*mq;
    float rq = rsqrtf(vq + 1e-5f);
    float mk = ks * invN, vk = kss * invN - mk*mk;
    float rk = rsqrtf(vk + 1e-5f);
    float qn0 = (q0 - mq) * rq * gq[t]     + betaq[t];
    float qn1 = (q1 - mq) * rq * gq[t+512] + betaq[t+512];
    float kn0 = (k0 - mk) * rk * gk[t]     + betak[t];
    float kn1 = (k1 - mk) * rk * gk[t+512] + betak[t+512];

    bufA[t]     = make_float2(x0, kn0);
    bufA[t+512] = make_float2(x1, kn1);
    __syncthreads();
    float2* Z = fft1024(bufA, bufB, tw, t);

    {
        float2 z  = Z[t];
        float2 zn = Z[(1024 - t) & 1023];
        float2 xf = make_float2(0.5f*(z.x + zn.x), 0.5f*(z.y - zn.y));
        float2 df = make_float2(z.x - zn.x, z.y + zn.y);
        float2 kf = make_float2(0.5f*df.y, -0.5f*df.x);
        g_kx[(size_t)row*NF + t] = cmulf(xf, kf);
        if (t == 0) {
            float2 z5 = Z[512];
            g_kx[(size_t)row*NF + 512] = make_float2(z5.x * z5.y, 0.f);
        }
    }
    __syncthreads();

    bufA[t]     = make_float2(qn0, 0.f);
    bufA[t+512] = make_float2(qn1, 0.f);
    __syncthreads();
    float2* Q = fft1024(bufA, bufB, tw, t);
    g_qf[(size_t)row*NF + t] = Q[t];
    if (t == 0) g_qf[(size_t)row*NF + 512] = Q[512];
}

// ---------------- reduce S_freq[b] = sum_s Kx[b,s] ----------------
__global__ void __launch_bounds__(256) reduce_s_kernel() {
    const int b = blockIdx.x;
    const int j = blockIdx.y;
    const int t = threadIdx.x;
    float2 acc = make_float2(0.f, 0.f);
    const float2* p = g_kx + (size_t)b * SEQ * NF + j;
    for (int s = t; s < SEQ; s += 256) {
        float2 v = p[(size_t)s * NF];
        acc.x += v.x; acc.y += v.y;
    }
    __shared__ float2 red[256];
    red[t] = acc;
    __syncthreads();
    for (int o = 128; o; o >>= 1) {
        if (t < o) { red[t].x += red[t+o].x; red[t].y += red[t+o].y; }
        __syncthreads();
    }
    if (t == 0) g_sf[b * NF + j] = red[0];
}

// ---------------- inverse FFT of mixF = Kx + S*conj(Qf); LN(x + mix) ----------------
__global__ void __launch_bounds__(512) fft_inv_ln_kernel(
    const float* __restrict__ x,
    const float* __restrict__ g0, const float* __restrict__ beta0)
{
    const int row = blockIdx.x;
    const int b = row >> 12;
    const int t = threadIdx.x;
    __shared__ float2 tw[512];
    __shared__ float2 bufA[1024];
    __shared__ float2 bufB[1024];
    __shared__ float  red[16];

    {
        float s_, c_;
        sincospif((float)t * (1.0f/512.0f), &s_, &c_);
        tw[t] = make_float2(c_, -s_);
    }

    {
        float2 kx = g_kx[(size_t)row*NF + t];
        float2 sf = g_sf[b*NF + t];
        float2 qf = g_qf[(size_t)row*NF + t];
        float2 qc = make_float2(qf.x, -qf.y);
        float2 p  = cmulf(sf, qc);
        float2 mv = make_float2(kx.x + p.x, kx.y + p.y);
        bufA[t] = make_float2(mv.x, -mv.y);
        if (t > 0) bufA[1024 - t] = mv;
        if (t == 0) {
            float2 kx5 = g_kx[(size_t)row*NF + 512];
            float2 sf5 = g_sf[b*NF + 512];
            float2 qf5 = g_qf[(size_t)row*NF + 512];
            float2 qc5 = make_float2(qf5.x, -qf5.y);
            float2 p5  = cmulf(sf5, qc5);
            bufA[512] = make_float2(kx5.x + p5.x, -(kx5.y + p5.y));
        }
    }
    __syncthreads();
    float2* R = fft1024(bufA, bufB, tw, t);

    const float invN = 1.0f / 1024.0f;
    const float* xr = x + (size_t)row * DIMS;
    float y0 = xr[t]     + R[t].x     * invN;
    float y1 = xr[t+512] + R[t+512].x * invN;

    float s  = block_sum512(y0 + y1, red);
    float ss = block_sum512(y0*y0 + y1*y1, red);
    float m = s * invN, v = ss * invN - m*m;
    float r = rsqrtf(v + 1e-5f);
    float o0 = (y0 - m) * r * g0[t]     + beta0[t];
    float o1 = (y1 - m) * r * g0[t+512] + beta0[t+512];
    float* o  = g_x1  + (size_t)row * DIMS;
    float* orr = g_x1r + (size_t)row * DIMS;
    o[t]      = o0;
    o[t+512]  = o1;
    orr[t]     = f2tf32f(o0);
    orr[t+512] = f2tf32f(o1);
}

// ---------------- out = LN(x1 + ff) ----------------
__global__ void __launch_bounds__(512) resid_ln_kernel(
    const float* __restrict__ g1v, const float* __restrict__ beta1,
    float* __restrict__ out)
{
    const int row = blockIdx.x;
    const int t = threadIdx.x;
    __shared__ float red[16];
    const float* a = g_x1 + (size_t)row * DIMS;
    const float* f = g_ff + (size_t)row * DIMS;
    float y0 = a[t]     + f[t];
    float y1 = a[t+512] + f[t+512];
    const float invN = 1.0f / 1024.0f;
    float s  = block_sum512(y0 + y1, red);
    float ss = block_sum512(y0*y0 + y1*y1, red);
    float m = s * invN, v = ss * invN - m*m;
    float r = rsqrtf(v + 1e-5f);
    float* o = out + (size_t)row * DIMS;
    o[t]     = (y0 - m) * r * g1v[t]     + beta1[t];
    o[t+512] = (y1 - m) * r * g1v[t+512] + beta1[t+512];
}

// ---------------- launch ----------------
extern "C" void kernel_launch(void* const* d_in, const int* in_sizes, int n_in,
                              void* d_out, int out_size)
{
    const float* x     = (const float*)d_in[0];
    const float* Wq    = (const float*)d_in[1];
    const float* bq    = (const float*)d_in[2];
    const float* gq    = (const float*)d_in[3];
    const float* betaq = (const float*)d_in[4];
    const float* Wk    = (const float*)d_in[5];
    const float* bk    = (const float*)d_in[6];
    const float* gk    = (const float*)d_in[7];
    const float* betak = (const float*)d_in[8];
    const float* g0    = (const float*)d_in[9];
    const float* beta0 = (const float*)d_in[10];
    const float* W1    = (const float*)d_in[11];
    const float* b1    = (const float*)d_in[12];
    const float* W2    = (const float*)d_in[13];
    const float* b2    = (const float*)d_in[14];
    const float* g1    = (const float*)d_in[15];
    const float* beta1 = (const float*)d_in[16];
    float* out = (float*)d_out;

    float *pqk, *px1r, *ph, *pff, *pxr, *pwr, *pbr;
    cudaGetSymbolAddress((void**)&pqk,  g_qk);
    cudaGetSymbolAddress((void**)&px1r, g_x1r);
    cudaGetSymbolAddress((void**)&ph,   g_h);
    cudaGetSymbolAddress((void**)&pff,  g_ff);
    cudaGetSymbolAddress((void**)&pxr,  g_xr);
    cudaGetSymbolAddress((void**)&pwr,  g_wr);
    cudaGetSymbolAddress((void**)&pbr,  g_br);

    const int SMEM = NSTAGE * STAGE_FLOATS * 4;  // 110592 B
    cudaFuncSetAttribute(gemm_mma<0,0>, cudaFuncAttributeMaxDynamicSharedMemorySize, SMEM);
    cudaFuncSetAttribute(gemm_mma<1,1>, cudaFuncAttributeMaxDynamicSharedMemorySize, SMEM);

    // tf32-round operands once (rna), pack Wq|Wk and bq|bk
    {
        int n;
        n = ROWS * DIMS / 4;   round_kernel<<<(n+255)/256, 256>>>(x,  pxr, n);
        n = DIMS * DIMS / 4;   round_kernel<<<(n+255)/256, 256>>>(Wq, pwr + WQK_OFF, n);
        n = DIMS * DIMS / 4;   round_kernel<<<(n+255)/256, 256>>>(Wk, pwr + WQK_OFF + DIMS*DIMS, n);
        n = FFD * DIMS / 4;    round_kernel<<<(n+255)/256, 256>>>(W1, pwr + W1_OFF, n);
        n = DIMS * FFD / 4;    round_kernel<<<(n+255)/256, 256>>>(W2, pwr + W2_OFF, n);
        pack_bias_kernel<<<(DIMS+255)/256, 256>>>(bq, bk);
    }

    // [q|k] = x @ [Wq|Wk]^T + [bq|bk]   (fused, N=2048)
    gemm_mma<0,0><<<dim3(2*DIMS/128, ROWS/128), 256, SMEM>>>(pxr, pwr + WQK_OFF, pbr, pqk, 2*DIMS, DIMS);
    // LN(q), LN(k), forward FFTs, Kx, Qf
    fft_fwd_kernel<<<ROWS, 512>>>(x, gq, betaq, gk, betak);
    // S = sum_s Kx (freq domain)
    reduce_s_kernel<<<dim3(BATCH, NF), 256>>>();
    // mix = irfft(Kx + S*conj(Qf)); x1 = LN(x + mix); also tf32-rounded copy
    fft_inv_ln_kernel<<<ROWS, 512>>>(x, g0, beta0);
    // h = round(relu(x1 @ W1^T + b1))
    gemm_mma<1,1><<<dim3(FFD/128, ROWS/128), 256, SMEM>>>(px1r, pwr + W1_OFF, b1, ph, FFD, DIMS);
    // ff = h @ W2^T + b2
    gemm_mma<0,0><<<dim3(DIMS/128, ROWS/128), 256, SMEM>>>(ph, pwr + W2_OFF, b2, pff, DIMS, FFD);
    // out = LN(x1 + ff)
    resid_ln_kernel<<<ROWS, 512>>>(g1, beta1, out);
}

// round 6
// speedup vs baseline: 3.8339x; 1.7353x over previous
#include <cuda_runtime.h>
#include <cuda_fp16.h>
#include <math.h>
#include <stdint.h>

#define DIMS 1024
#define FFD  4096
#define BATCH 4
#define SEQ  4096
#define ROWS (BATCH*SEQ)   // 16384
#define NF   513           // rfft bins for N=1024

// ---------------- scratch (device globals; no allocation allowed) ----------------
__device__ float  g_qk [(size_t)ROWS*2*DIMS];   // q | k packed (N=2048 GEMM out)
__device__ float  g_x1 [(size_t)ROWS*DIMS];     // LN output (residual, fp32)
__device__ __half g_x1h[(size_t)ROWS*DIMS];     // fp16 copy (GEMM input)
__device__ float  g_ff [(size_t)ROWS*DIMS];
__device__ __half g_h  [(size_t)ROWS*FFD];      // FFN hidden, fp16
__device__ __half g_xh [(size_t)ROWS*DIMS];     // x in fp16
__device__ __half g_wh [(size_t)(2*DIMS*DIMS + 2*DIMS*FFD)]; // Wqk | W1 | W2 fp16
__device__ float  g_br [2*DIMS];                // bq | bk packed
__device__ float2 g_kx[(size_t)ROWS*NF];
__device__ float2 g_qf[(size_t)ROWS*NF];
__device__ float2 g_sf[BATCH*NF];

#define WQK_OFF 0
#define W1_OFF  (2*DIMS*DIMS)
#define W2_OFF  (2*DIMS*DIMS + DIMS*FFD)

// ---------------- PTX helpers ----------------
__device__ __forceinline__ uint32_t smem_u32(const void* p) {
    uint32_t a;
    asm("{ .reg .u64 t; cvta.to.shared.u64 t, %1; cvt.u32.u64 %0, t; }" : "=r"(a) : "l"(p));
    return a;
}
__device__ __forceinline__ uint32_t h2_as_u32(__half2 h) {
    union { __half2 h; uint32_t u; } cvt;
    cvt.h = h;
    return cvt.u;
}
__device__ __forceinline__ void cp16(uint32_t dst, const void* src) {
    asm volatile("cp.async.cg.shared.global [%0], [%1], 16;" :: "r"(dst), "l"(src));
}
#define CP_COMMIT() asm volatile("cp.async.commit_group;" ::: "memory")
template<int N> __device__ __forceinline__ void cp_wait() {
    asm volatile("cp.async.wait_group %0;" :: "n"(N) : "memory");
}
__device__ __forceinline__ void mma_f16(float& c0, float& c1, float& c2, float& c3,
                                        uint32_t a0, uint32_t a1, uint32_t a2, uint32_t a3,
                                        uint32_t b0, uint32_t b1) {
    asm volatile(
        "mma.sync.aligned.m16n8k16.row.col.f32.f16.f16.f32 "
        "{%0,%1,%2,%3}, {%4,%5,%6,%7}, {%8,%9}, {%0,%1,%2,%3};"
        : "+f"(c0), "+f"(c1), "+f"(c2), "+f"(c3)
        : "r"(a0), "r"(a1), "r"(a2), "r"(a3), "r"(b0), "r"(b1));
}
__device__ __forceinline__ void ldsm_x4(uint32_t& r0, uint32_t& r1, uint32_t& r2, uint32_t& r3,
                                        uint32_t addr) {
    asm volatile("ldmatrix.sync.aligned.m8n8.x4.shared.b16 {%0,%1,%2,%3}, [%4];"
                 : "=r"(r0), "=r"(r1), "=r"(r2), "=r"(r3) : "r"(addr));
}

// ---------------- fp32 -> fp16 convert pre-passes ----------------
__global__ void __launch_bounds__(256) conv_h_kernel(const float* __restrict__ src,
                                                     __half* __restrict__ dst, int n8) {
    int i = blockIdx.x * 256 + threadIdx.x;
    if (i < n8) {
        float4 a = ((const float4*)src)[2*i];
        float4 b = ((const float4*)src)[2*i+1];
        uint4 o;
        o.x = h2_as_u32(__floats2half2_rn(a.x, a.y));
        o.y = h2_as_u32(__floats2half2_rn(a.z, a.w));
        o.z = h2_as_u32(__floats2half2_rn(b.x, b.y));
        o.w = h2_as_u32(__floats2half2_rn(b.z, b.w));
        ((uint4*)dst)[i] = o;
    }
}
__global__ void pack_bias_kernel(const float* __restrict__ bq, const float* __restrict__ bk) {
    int i = blockIdx.x * 256 + threadIdx.x;
    if (i < DIMS) { g_br[i] = bq[i]; g_br[i + DIMS] = bk[i]; }
}

// ======================= mma.sync fp16 GEMM =======================
// C[M,N] = A[M,K]*B[N,K]^T + bias. A,B fp16 K-contiguous. 128x128x64 CTA tile,
// 256 threads (8 warps 2Mx4N, warp tile 64x32), 3-stage cp.async pipeline.
// Padded shared row stride 144 B (72 halves) -> conflict-free ldmatrix.
#define BK 64
#define LDH 72                      // halves per padded row
#define ROWB 144                    // bytes per padded row
#define TILE_BYTES (128*ROWB)       // 18432
#define STAGE_BYTES (2*TILE_BYTES)  // 36864
#define NSTAGE 3

template<int RELU, typename CT>
__global__ void __launch_bounds__(256)
gemm_h(const __half* __restrict__ A, const __half* __restrict__ B,
       const float* __restrict__ bias, CT* __restrict__ C,
       int N, int K)
{
    extern __shared__ char smem[];
    const int tid = threadIdx.x;
    const int warp = tid >> 5;
    const int lane = tid & 31;
    const int wm = warp & 1;
    const int wn = warp >> 1;
    const int lr = lane >> 2;
    const int lc = lane & 3;

    const __half* Ab = A + (size_t)blockIdx.y * 128 * K;
    const __half* Bb = B + (size_t)blockIdx.x * 128 * K;

    const uint32_t sbase = smem_u32(smem);
    const int row = tid >> 1;      // 0..127
    const int hpart = tid & 1;     // 0..1 (which 64B half of the 128B row)
    const int ktiles = K / BK;

    // ldmatrix lane base offsets (bytes, relative to tile start)
    uint32_t aoff[4];
    {
        const int l7 = lane & 7;
        const int rsel = (lane >> 3) & 1;
        const int csel = lane >> 4;
        #pragma unroll
        for (int mt = 0; mt < 4; mt++) {
            int r = wm * 64 + mt * 16 + l7 + rsel * 8;
            aoff[mt] = (uint32_t)(r * ROWB + csel * 16);
        }
    }
    uint32_t boff[2];
    {
        const int l7 = lane & 7;
        const int csel = (lane >> 3) & 1;
        const int rsel = lane >> 4;
        #pragma unroll
        for (int pr = 0; pr < 2; pr++) {
            int r = wn * 32 + pr * 16 + rsel * 8 + l7;
            boff[pr] = (uint32_t)(r * ROWB + csel * 16);
        }
    }

    auto load_stage = [&](int stage, int kt) {
        const int k0 = kt * BK;
        const uint32_t sA = sbase + stage * STAGE_BYTES;
        const uint32_t sB = sA + TILE_BYTES;
        const __half* ga = Ab + (size_t)row * K + k0 + hpart * 32;
        const __half* gb = Bb + (size_t)row * K + k0 + hpart * 32;
        const uint32_t so = (uint32_t)(row * ROWB + hpart * 64);
        #pragma unroll
        for (int c = 0; c < 4; c++) {
            cp16(sA + so + c * 16, ga + c * 8);
            cp16(sB + so + c * 16, gb + c * 8);
        }
    };

    load_stage(0, 0); CP_COMMIT();
    load_stage(1, 1); CP_COMMIT();

    float acc[4][4][4];
    #pragma unroll
    for (int i = 0; i < 4; i++)
        #pragma unroll
        for (int j = 0; j < 4; j++)
            #pragma unroll
            for (int r = 0; r < 4; r++) acc[i][j][r] = 0.f;

    for (int it = 0; it < ktiles; it++) {
        cp_wait<1>();
        __syncthreads();

        const uint32_t sA = sbase + (it % NSTAGE) * STAGE_BYTES;
        const uint32_t sB = sA + TILE_BYTES;

        const int nt2 = it + 2;
        if (nt2 < ktiles) load_stage(nt2 % NSTAGE, nt2);
        CP_COMMIT();

        #pragma unroll
        for (int ks = 0; ks < 4; ks++) {              // 4 x k16 per BK=64
            const uint32_t kb = ks * 32;              // 16 halves = 32 B
            uint32_t a[4][4], b[4][2];
            #pragma unroll
            for (int mt = 0; mt < 4; mt++)
                ldsm_x4(a[mt][0], a[mt][1], a[mt][2], a[mt][3], sA + aoff[mt] + kb);
            #pragma unroll
            for (int pr = 0; pr < 2; pr++)
                ldsm_x4(b[2*pr][0], b[2*pr][1], b[2*pr+1][0], b[2*pr+1][1],
                        sB + boff[pr] + kb);
            #pragma unroll
            for (int mt = 0; mt < 4; mt++)
                #pragma unroll
                for (int nt = 0; nt < 4; nt++)
                    mma_f16(acc[mt][nt][0], acc[mt][nt][1],
                            acc[mt][nt][2], acc[mt][nt][3],
                            a[mt][0], a[mt][1], a[mt][2], a[mt][3],
                            b[nt][0], b[nt][1]);
        }
        __syncthreads();
    }

    // epilogue: accum layout (m16n8): v0,v1 -> (lr, lc*2(+1)); v2,v3 -> (lr+8, ...)
    const int crow0 = blockIdx.y * 128 + wm * 64;
    const int ccol0 = blockIdx.x * 128 + wn * 32;
    #pragma unroll
    for (int mt = 0; mt < 4; mt++) {
        #pragma unroll
        for (int nt = 0; nt < 4; nt++) {
            const int r0 = crow0 + mt * 16 + lr;
            const int c0 = ccol0 + nt * 8 + lc * 2;
            float b0 = __ldg(bias + c0);
            float b1 = __ldg(bias + c0 + 1);
            float v0 = acc[mt][nt][0] + b0;
            float v1 = acc[mt][nt][1] + b1;
            float v2 = acc[mt][nt][2] + b0;
            float v3 = acc[mt][nt][3] + b1;
            if (RELU) {
                v0 = fmaxf(v0, 0.f); v1 = fmaxf(v1, 0.f);
                v2 = fmaxf(v2, 0.f); v3 = fmaxf(v3, 0.f);
            }
            if (sizeof(CT) == 2) {
                __half2* p0 = (__half2*)((__half*)C + (size_t)r0 * N + c0);
                __half2* p1 = (__half2*)((__half*)C + (size_t)(r0 + 8) * N + c0);
                *p0 = __floats2half2_rn(v0, v1);
                *p1 = __floats2half2_rn(v2, v3);
            } else {
                *(float2*)((float*)C + (size_t)r0 * N + c0)       = make_float2(v0, v1);
                *(float2*)((float*)C + (size_t)(r0 + 8) * N + c0) = make_float2(v2, v3);
            }
        }
    }
}

// ---------------- helpers for FFT path ----------------
__device__ __forceinline__ float2 cmulf(float2 a, float2 b) {
    return make_float2(a.x*b.x - a.y*b.y, a.x*b.y + a.y*b.x);
}

__device__ __forceinline__ float block_sum512(float v, volatile float* red) {
    int t = threadIdx.x;
    #pragma unroll
    for (int o = 16; o; o >>= 1) v += __shfl_xor_sync(0xffffffffu, v, o);
    if ((t & 31) == 0) red[t >> 5] = v;
    __syncthreads();
    if (t == 0) {
        float s = 0.f;
        #pragma unroll
        for (int i = 0; i < 16; i++) s += red[i];
        red[0] = s;
    }
    __syncthreads();
    float r = red[0];
    __syncthreads();
    return r;
}

__device__ __forceinline__ float2* fft1024(float2* bufA, float2* bufB,
                                           const float2* tw, int t) {
    float2* src = bufA; float2* dst = bufB;
    #pragma unroll
    for (int m = 1; m <= 512; m <<= 1) {
        float2 a = src[t];
        float2 b = src[t + 512];
        int jm = t & ~(m - 1);
        float2 w = tw[jm];
        float2 s = make_float2(a.x + b.x, a.y + b.y);
        float2 d = make_float2(a.x - b.x, a.y - b.y);
        float2 r = make_float2(d.x*w.x - d.y*w.y, d.x*w.y + d.y*w.x);
        dst[t + jm]     = s;
        dst[t + jm + m] = r;
        __syncthreads();
        float2* tmp = src; src = dst; dst = tmp;
    }
    return src;
}

// ---------------- forward FFTs: LN(q), LN(k); Kx = Xf*Kf; Qf ----------------
__global__ void __launch_bounds__(512) fft_fwd_kernel(
    const float* __restrict__ x,
    const float* __restrict__ gq, const float* __restrict__ betaq,
    const float* __restrict__ gk, const float* __restrict__ betak)
{
    const int row = blockIdx.x;
    const int t = threadIdx.x;
    __shared__ float2 tw[512];
    __shared__ float2 bufA[1024];
    __shared__ float2 bufB[1024];
    __shared__ float  red[16];

    {
        float s_, c_;
        sincospif((float)t * (1.0f/512.0f), &s_, &c_);
        tw[t] = make_float2(c_, -s_);
    }

    const float* xr = x    + (size_t)row * DIMS;
    const float* qr = g_qk + (size_t)row * 2 * DIMS;
    const float* kr = qr + DIMS;
    float x0 = xr[t], x1 = xr[t+512];
    float q0 = qr[t], q1 = qr[t+512];
    float k0 = kr[t], k1 = kr[t+512];

    const float invN = 1.0f / 1024.0f;
    float qs  = block_sum512(q0 + q1, red);
    float qss = block_sum512(q0*q0 + q1*q1, red);
    float ks  = block_sum512(k0 + k1, red);
    float kss = block_sum512(k0*k0 + k1*k1, red);
    float mq = qs * invN, vq = qss * invN - mq*mq;
    float rq = rsqrtf(vq + 1e-5f);
    float mk = ks * invN, vk = kss * invN - mk*mk;
    float rk = rsqrtf(vk + 1e-5f);
    float qn0 = (q0 - mq) * rq * gq[t]     + betaq[t];
    float qn1 = (q1 - mq) * rq * gq[t+512] + betaq[t+512];
    float kn0 = (k0 - mk) * rk * gk[t]     + betak[t];
    float kn1 = (k1 - mk) * rk * gk[t+512] + betak[t+512];

    bufA[t]     = make_float2(x0, kn0);
    bufA[t+512] = make_float2(x1, kn1);
    __syncthreads();
    float2* Z = fft1024(bufA, bufB, tw, t);

    {
        float2 z  = Z[t];
        float2 zn = Z[(1024 - t) & 1023];
        float2 xf = make_float2(0.5f*(z.x + zn.x), 0.5f*(z.y - zn.y));
        float2 df = make_float2(z.x - zn.x, z.y + zn.y);
        float2 kf = make_float2(0.5f*df.y, -0.5f*df.x);
        g_kx[(size_t)row*NF + t] = cmulf(xf, kf);
        if (t == 0) {
            float2 z5 = Z[512];
            g_kx[(size_t)row*NF + 512] = make_float2(z5.x * z5.y, 0.f);
        }
    }
    __syncthreads();

    bufA[t]     = make_float2(qn0, 0.f);
    bufA[t+512] = make_float2(qn1, 0.f);
    __syncthreads();
    float2* Q = fft1024(bufA, bufB, tw, t);
    g_qf[(size_t)row*NF + t] = Q[t];
    if (t == 0) g_qf[(size_t)row*NF + 512] = Q[512];
}

// ---------------- reduce S_freq[b] = sum_s Kx[b,s] ----------------
__global__ void __launch_bounds__(256) reduce_s_kernel() {
    const int b = blockIdx.x;
    const int j = blockIdx.y;
    const int t = threadIdx.x;
    float2 acc = make_float2(0.f, 0.f);
    const float2* p = g_kx + (size_t)b * SEQ * NF + j;
    for (int s = t; s < SEQ; s += 256) {
        float2 v = p[(size_t)s * NF];
        acc.x += v.x; acc.y += v.y;
    }
    __shared__ float2 red[256];
    red[t] = acc;
    __syncthreads();
    for (int o = 128; o; o >>= 1) {
        if (t < o) { red[t].x += red[t+o].x; red[t].y += red[t+o].y; }
        __syncthreads();
    }
    if (t == 0) g_sf[b * NF + j] = red[0];
}

// ---------------- inverse FFT of mixF = Kx + S*conj(Qf); LN(x + mix) ----------------
__global__ void __launch_bounds__(512) fft_inv_ln_kernel(
    const float* __restrict__ x,
    const float* __restrict__ g0, const float* __restrict__ beta0)
{
    const int row = blockIdx.x;
    const int b = row >> 12;
    const int t = threadIdx.x;
    __shared__ float2 tw[512];
    __shared__ float2 bufA[1024];
    __shared__ float2 bufB[1024];
    __shared__ float  red[16];

    {
        float s_, c_;
        sincospif((float)t * (1.0f/512.0f), &s_, &c_);
        tw[t] = make_float2(c_, -s_);
    }

    {
        float2 kx = g_kx[(size_t)row*NF + t];
        float2 sf = g_sf[b*NF + t];
        float2 qf = g_qf[(size_t)row*NF + t];
        float2 qc = make_float2(qf.x, -qf.y);
        float2 p  = cmulf(sf, qc);
        float2 mv = make_float2(kx.x + p.x, kx.y + p.y);
        bufA[t] = make_float2(mv.x, -mv.y);
        if (t > 0) bufA[1024 - t] = mv;
        if (t == 0) {
            float2 kx5 = g_kx[(size_t)row*NF + 512];
            float2 sf5 = g_sf[b*NF + 512];
            float2 qf5 = g_qf[(size_t)row*NF + 512];
            float2 qc5 = make_float2(qf5.x, -qf5.y);
            float2 p5  = cmulf(sf5, qc5);
            bufA[512] = make_float2(kx5.x + p5.x, -(kx5.y + p5.y));
        }
    }
    __syncthreads();
    float2* R = fft1024(bufA, bufB, tw, t);

    const float invN = 1.0f / 1024.0f;
    const float* xr = x + (size_t)row * DIMS;
    float y0 = xr[t]     + R[t].x     * invN;
    float y1 = xr[t+512] + R[t+512].x * invN;

    float s  = block_sum512(y0 + y1, red);
    float ss = block_sum512(y0*y0 + y1*y1, red);
    float m = s * invN, v = ss * invN - m*m;
    float r = rsqrtf(v + 1e-5f);
    float o0 = (y0 - m) * r * g0[t]     + beta0[t];
    float o1 = (y1 - m) * r * g0[t+512] + beta0[t+512];
    float*  o  = g_x1  + (size_t)row * DIMS;
    __half* oh = g_x1h + (size_t)row * DIMS;
    o[t]      = o0;
    o[t+512]  = o1;
    oh[t]     = __float2half_rn(o0);
    oh[t+512] = __float2half_rn(o1);
}

// ---------------- out = LN(x1 + ff) ----------------
__global__ void __launch_bounds__(512) resid_ln_kernel(
    const float* __restrict__ g1v, const float* __restrict__ beta1,
    float* __restrict__ out)
{
    const int row = blockIdx.x;
    const int t = threadIdx.x;
    __shared__ float red[16];
    const float* a = g_x1 + (size_t)row * DIMS;
    const float* f = g_ff + (size_t)row * DIMS;
    float y0 = a[t]     + f[t];
    float y1 = a[t+512] + f[t+512];
    const float invN = 1.0f / 1024.0f;
    float s  = block_sum512(y0 + y1, red);
    float ss = block_sum512(y0*y0 + y1*y1, red);
    float m = s * invN, v = ss * invN - m*m;
    float r = rsqrtf(v + 1e-5f);
    float* o = out + (size_t)row * DIMS;
    o[t]     = (y0 - m) * r * g1v[t]     + beta1[t];
    o[t+512] = (y1 - m) * r * g1v[t+512] + beta1[t+512];
}

// ---------------- launch ----------------
extern "C" void kernel_launch(void* const* d_in, const int* in_sizes, int n_in,
                              void* d_out, int out_size)
{
    const float* x     = (const float*)d_in[0];
    const float* Wq    = (const float*)d_in[1];
    const float* bq    = (const float*)d_in[2];
    const float* gq    = (const float*)d_in[3];
    const float* betaq = (const float*)d_in[4];
    const float* Wk    = (const float*)d_in[5];
    const float* bk    = (const float*)d_in[6];
    const float* gk    = (const float*)d_in[7];
    const float* betak = (const float*)d_in[8];
    const float* g0    = (const float*)d_in[9];
    const float* beta0 = (const float*)d_in[10];
    const float* W1    = (const float*)d_in[11];
    const float* b1    = (const float*)d_in[12];
    const float* W2    = (const float*)d_in[13];
    const float* b2    = (const float*)d_in[14];
    const float* g1    = (const float*)d_in[15];
    const float* beta1 = (const float*)d_in[16];
    float* out = (float*)d_out;

    float *pqk, *pff, *pbr;
    __half *px1h, *ph, *pxh, *pwh;
    cudaGetSymbolAddress((void**)&pqk,  g_qk);
    cudaGetSymbolAddress((void**)&px1h, g_x1h);
    cudaGetSymbolAddress((void**)&ph,   g_h);
    cudaGetSymbolAddress((void**)&pff,  g_ff);
    cudaGetSymbolAddress((void**)&pxh,  g_xh);
    cudaGetSymbolAddress((void**)&pwh,  g_wh);
    cudaGetSymbolAddress((void**)&pbr,  g_br);

    const int SMEM = NSTAGE * STAGE_BYTES;  // 110592 B
    cudaFuncSetAttribute(gemm_h<0,float>,  cudaFuncAttributeMaxDynamicSharedMemorySize, SMEM);
    cudaFuncSetAttribute(gemm_h<1,__half>, cudaFuncAttributeMaxDynamicSharedMemorySize, SMEM);

    // fp16 conversions (rn), pack Wq|Wk and bq|bk
    {
        int n;
        n = ROWS * DIMS / 8;   conv_h_kernel<<<(n+255)/256, 256>>>(x,  pxh, n);
        n = DIMS * DIMS / 8;   conv_h_kernel<<<(n+255)/256, 256>>>(Wq, pwh + WQK_OFF, n);
        n = DIMS * DIMS / 8;   conv_h_kernel<<<(n+255)/256, 256>>>(Wk, pwh + WQK_OFF + DIMS*DIMS, n);
        n = FFD * DIMS / 8;    conv_h_kernel<<<(n+255)/256, 256>>>(W1, pwh + W1_OFF, n);
        n = DIMS * FFD / 8;    conv_h_kernel<<<(n+255)/256, 256>>>(W2, pwh + W2_OFF, n);
        pack_bias_kernel<<<(DIMS+255)/256, 256>>>(bq, bk);
    }

    // [q|k] = x @ [Wq|Wk]^T + [bq|bk]   (fused, N=2048, fp16 MMA)
    gemm_h<0,float><<<dim3(2*DIMS/128, ROWS/128), 256, SMEM>>>(pxh, pwh + WQK_OFF, pbr, pqk, 2*DIMS, DIMS);
    // LN(q), LN(k), forward FFTs, Kx, Qf
    fft_fwd_kernel<<<ROWS, 512>>>(x, gq, betaq, gk, betak);
    // S = sum_s Kx (freq domain)
    reduce_s_kernel<<<dim3(BATCH, NF), 256>>>();
    // mix = irfft(Kx + S*conj(Qf)); x1 = LN(x + mix) (+fp16 copy)
    fft_inv_ln_kernel<<<ROWS, 512>>>(x, g0, beta0);
    // h = relu(x1 @ W1^T + b1)  -> fp16
    gemm_h<1,__half><<<dim3(FFD/128, ROWS/128), 256, SMEM>>>(px1h, pwh + W1_OFF, b1, ph, FFD, DIMS);
    // ff = h @ W2^T + b2
    gemm_h<0,float><<<dim3(DIMS/128, ROWS/128), 256, SMEM>>>(ph, pwh + W2_OFF, b2, pff, DIMS, FFD);
    // out = LN(x1 + ff)
    resid_ln_kernel<<<ROWS, 512>>>(g1, beta1, out);
}

// round 7
// speedup vs baseline: 5.0062x; 1.3058x over previous
#include <cuda_runtime.h>
#include <cuda_fp16.h>
#include <math.h>
#include <stdint.h>

#define DIMS 1024
#define FFD  4096
#define BATCH 4
#define SEQ  4096
#define ROWS (BATCH*SEQ)   // 16384
#define NF   513           // rfft bins for N=1024

// ---------------- scratch (device globals; no allocation allowed) ----------------
__device__ float  g_qk [(size_t)ROWS*2*DIMS];   // q | k packed (N=2048 GEMM out)
__device__ float  g_x1 [(size_t)ROWS*DIMS];     // LN output (residual, fp32)
__device__ __half g_x1h[(size_t)ROWS*DIMS];     // fp16 copy (GEMM input)
__device__ float  g_ff [(size_t)ROWS*DIMS];
__device__ __half g_h  [(size_t)ROWS*FFD];      // FFN hidden, fp16
__device__ __half g_xh [(size_t)ROWS*DIMS];     // x in fp16
__device__ __half g_wh [(size_t)(2*DIMS*DIMS + 2*DIMS*FFD)]; // Wqk | W1 | W2 fp16
__device__ float  g_br [2*DIMS];                // bq | bk packed
__device__ float2 g_kx[(size_t)ROWS*NF];
__device__ float2 g_qf[(size_t)ROWS*NF];
__device__ float2 g_sf[BATCH*NF];

#define WQK_OFF 0
#define W1_OFF  (2*DIMS*DIMS)
#define W2_OFF  (2*DIMS*DIMS + DIMS*FFD)

// ---------------- PTX helpers ----------------
__device__ __forceinline__ uint32_t smem_u32(const void* p) {
    uint32_t a;
    asm("{ .reg .u64 t; cvta.to.shared.u64 t, %1; cvt.u32.u64 %0, t; }" : "=r"(a) : "l"(p));
    return a;
}
__device__ __forceinline__ uint32_t h2_as_u32(__half2 h) {
    union { __half2 h; uint32_t u; } cvt;
    cvt.h = h;
    return cvt.u;
}
__device__ __forceinline__ void cp16(uint32_t dst, const void* src) {
    asm volatile("cp.async.cg.shared.global [%0], [%1], 16;" :: "r"(dst), "l"(src));
}
#define CP_COMMIT() asm volatile("cp.async.commit_group;" ::: "memory")
template<int N> __device__ __forceinline__ void cp_wait() {
    asm volatile("cp.async.wait_group %0;" :: "n"(N) : "memory");
}
__device__ __forceinline__ void mma_f16(float& c0, float& c1, float& c2, float& c3,
                                        uint32_t a0, uint32_t a1, uint32_t a2, uint32_t a3,
                                        uint32_t b0, uint32_t b1) {
    asm volatile(
        "mma.sync.aligned.m16n8k16.row.col.f32.f16.f16.f32 "
        "{%0,%1,%2,%3}, {%4,%5,%6,%7}, {%8,%9}, {%0,%1,%2,%3};"
        : "+f"(c0), "+f"(c1), "+f"(c2), "+f"(c3)
        : "r"(a0), "r"(a1), "r"(a2), "r"(a3), "r"(b0), "r"(b1));
}
__device__ __forceinline__ void ldsm_x4(uint32_t& r0, uint32_t& r1, uint32_t& r2, uint32_t& r3,
                                        uint32_t addr) {
    asm volatile("ldmatrix.sync.aligned.m8n8.x4.shared.b16 {%0,%1,%2,%3}, [%4];"
                 : "=r"(r0), "=r"(r1), "=r"(r2), "=r"(r3) : "r"(addr));
}

// ---------------- fp32 -> fp16 convert pre-passes ----------------
__global__ void __launch_bounds__(256) conv_h_kernel(const float* __restrict__ src,
                                                     __half* __restrict__ dst, int n8) {
    int i = blockIdx.x * 256 + threadIdx.x;
    if (i < n8) {
        float4 a = ((const float4*)src)[2*i];
        float4 b = ((const float4*)src)[2*i+1];
        uint4 o;
        o.x = h2_as_u32(__floats2half2_rn(a.x, a.y));
        o.y = h2_as_u32(__floats2half2_rn(a.z, a.w));
        o.z = h2_as_u32(__floats2half2_rn(b.x, b.y));
        o.w = h2_as_u32(__floats2half2_rn(b.z, b.w));
        ((uint4*)dst)[i] = o;
    }
}
__global__ void pack_bias_kernel(const float* __restrict__ bq, const float* __restrict__ bk) {
    int i = blockIdx.x * 256 + threadIdx.x;
    if (i < DIMS) { g_br[i] = bq[i]; g_br[i + DIMS] = bk[i]; }
}

// ======================= mma.sync fp16 GEMM =======================
// C[M,N] = A[M,K]*B[N,K]^T + bias. A,B fp16 K-contiguous.
// 256x128x64 CTA tile, 256 threads (8 warps = 4M x 2N, warp tile 64x64),
// 3-stage cp.async pipeline, padded row stride 144 B.
#define BK 64
#define ROWB 144
#define A_TILE_BYTES (256*ROWB)                  // 36864
#define B_TILE_BYTES (128*ROWB)                  // 18432
#define STAGE_BYTES (A_TILE_BYTES + B_TILE_BYTES) // 55296
#define NSTAGE 3

template<int RELU, typename CT>
__global__ void __launch_bounds__(256, 1)
gemm_h(const __half* __restrict__ A, const __half* __restrict__ B,
       const float* __restrict__ bias, CT* __restrict__ C,
       int N, int K)
{
    extern __shared__ char smem[];
    const int tid = threadIdx.x;
    const int warp = tid >> 5;
    const int lane = tid & 31;
    const int wm = warp >> 1;     // 0..3 (M)
    const int wn = warp & 1;      // 0..1 (N)
    const int lr = lane >> 2;
    const int lc = lane & 3;

    const __half* Ab = A + (size_t)blockIdx.y * 256 * K;
    const __half* Bb = B + (size_t)blockIdx.x * 128 * K;

    const uint32_t sbase = smem_u32(smem);
    const int ktiles = K / BK;

    // ldmatrix lane base offsets (bytes, relative to region start)
    uint32_t aoff[4];
    {
        const int l7 = lane & 7;
        const int rsel = (lane >> 3) & 1;
        const int csel = lane >> 4;
        #pragma unroll
        for (int mt = 0; mt < 4; mt++) {
            int r = wm * 64 + mt * 16 + l7 + rsel * 8;
            aoff[mt] = (uint32_t)(r * ROWB + csel * 16);
        }
    }
    uint32_t boff[4];
    {
        const int l7 = lane & 7;
        const int csel = (lane >> 3) & 1;
        const int rsel = lane >> 4;
        #pragma unroll
        for (int pr = 0; pr < 4; pr++) {
            int r = wn * 64 + pr * 16 + rsel * 8 + l7;
            boff[pr] = (uint32_t)(r * ROWB + csel * 16);
        }
    }

    auto load_stage = [&](int stage, int kt) {
        const int k0 = kt * BK;
        const uint32_t sA = sbase + stage * STAGE_BYTES;
        const uint32_t sB = sA + A_TILE_BYTES;
        #pragma unroll
        for (int i = 0; i < 8; i++) {
            int g = i * 256 + tid;
            int r = g >> 3, c = g & 7;
            cp16(sA + r * ROWB + c * 16, Ab + (size_t)r * K + k0 + c * 8);
        }
        #pragma unroll
        for (int i = 0; i < 4; i++) {
            int g = i * 256 + tid;
            int r = g >> 3, c = g & 7;
            cp16(sB + r * ROWB + c * 16, Bb + (size_t)r * K + k0 + c * 8);
        }
    };

    load_stage(0, 0); CP_COMMIT();
    load_stage(1, 1); CP_COMMIT();

    float acc[4][8][4];
    #pragma unroll
    for (int i = 0; i < 4; i++)
        #pragma unroll
        for (int j = 0; j < 8; j++)
            #pragma unroll
            for (int r = 0; r < 4; r++) acc[i][j][r] = 0.f;

    for (int it = 0; it < ktiles; it++) {
        cp_wait<1>();
        __syncthreads();

        const uint32_t sA = sbase + (it % NSTAGE) * STAGE_BYTES;
        const uint32_t sB = sA + A_TILE_BYTES;

        const int nt2 = it + 2;
        if (nt2 < ktiles) load_stage(nt2 % NSTAGE, nt2);
        CP_COMMIT();

        #pragma unroll
        for (int ks = 0; ks < 4; ks++) {
            const uint32_t kb = ks * 32;
            uint32_t a[4][4], b[8][2];
            #pragma unroll
            for (int mt = 0; mt < 4; mt++)
                ldsm_x4(a[mt][0], a[mt][1], a[mt][2], a[mt][3], sA + aoff[mt] + kb);
            #pragma unroll
            for (int pr = 0; pr < 4; pr++)
                ldsm_x4(b[2*pr][0], b[2*pr][1], b[2*pr+1][0], b[2*pr+1][1],
                        sB + boff[pr] + kb);
            #pragma unroll
            for (int mt = 0; mt < 4; mt++)
                #pragma unroll
                for (int nt = 0; nt < 8; nt++)
                    mma_f16(acc[mt][nt][0], acc[mt][nt][1],
                            acc[mt][nt][2], acc[mt][nt][3],
                            a[mt][0], a[mt][1], a[mt][2], a[mt][3],
                            b[nt][0], b[nt][1]);
        }
        __syncthreads();
    }

    // epilogue
    const int crow0 = blockIdx.y * 256 + wm * 64;
    const int ccol0 = blockIdx.x * 128 + wn * 64;
    float bb0[8], bb1[8];
    #pragma unroll
    for (int nt = 0; nt < 8; nt++) {
        bb0[nt] = __ldg(bias + ccol0 + nt * 8 + lc * 2);
        bb1[nt] = __ldg(bias + ccol0 + nt * 8 + lc * 2 + 1);
    }
    #pragma unroll
    for (int mt = 0; mt < 4; mt++) {
        #pragma unroll
        for (int nt = 0; nt < 8; nt++) {
            const int r0 = crow0 + mt * 16 + lr;
            const int c0 = ccol0 + nt * 8 + lc * 2;
            float v0 = acc[mt][nt][0] + bb0[nt];
            float v1 = acc[mt][nt][1] + bb1[nt];
            float v2 = acc[mt][nt][2] + bb0[nt];
            float v3 = acc[mt][nt][3] + bb1[nt];
            if (RELU) {
                v0 = fmaxf(v0, 0.f); v1 = fmaxf(v1, 0.f);
                v2 = fmaxf(v2, 0.f); v3 = fmaxf(v3, 0.f);
            }
            if (sizeof(CT) == 2) {
                *(__half2*)((__half*)C + (size_t)r0 * N + c0)       = __floats2half2_rn(v0, v1);
                *(__half2*)((__half*)C + (size_t)(r0 + 8) * N + c0) = __floats2half2_rn(v2, v3);
            } else {
                *(float2*)((float*)C + (size_t)r0 * N + c0)       = make_float2(v0, v1);
                *(float2*)((float*)C + (size_t)(r0 + 8) * N + c0) = make_float2(v2, v3);
            }
        }
    }
}

// ---------------- FFT path helpers ----------------
__device__ __forceinline__ float2 cmulf(float2 a, float2 b) {
    return make_float2(a.x*b.x - a.y*b.y, a.x*b.y + a.y*b.x);
}
// shared-bank swizzle (bijection on [0,1024))
#define F(i) ((i) ^ ((((i) >> 5) & 7) << 2))

__device__ __forceinline__ float2 block_sum2_256(float2 v, volatile float2* red) {
    int t = threadIdx.x;
    #pragma unroll
    for (int o = 16; o; o >>= 1) {
        v.x += __shfl_xor_sync(0xffffffffu, v.x, o);
        v.y += __shfl_xor_sync(0xffffffffu, v.y, o);
    }
    if ((t & 31) == 0) { red[t >> 5].x = v.x; red[t >> 5].y = v.y; }
    __syncthreads();
    if (t == 0) {
        float2 s = make_float2(0.f, 0.f);
        #pragma unroll
        for (int i = 0; i < 8; i++) { s.x += red[i].x; s.y += red[i].y; }
        red[0].x = s.x; red[0].y = s.y;
    }
    __syncthreads();
    float2 r = make_float2(red[0].x, red[0].y);
    __syncthreads();
    return r;
}

// 1024-pt radix-4 Stockham FFT (forward, exp(-2pi i k n/N)), 256 threads,
// one radix-4 butterfly per thread per stage. Twiddle table tw[0..767]:
// tw[i] = exp(-2pi i * i/1024). Caller syncs after filling bufA (swizzled F).
// Result ends in bufB (5 stages).
__device__ __forceinline__ void fft1024_r4(float2* bufA, float2* bufB,
                                           const float2* tw, int v) {
    float2* src = bufA; float2* dst = bufB;
    #pragma unroll
    for (int st = 0; st < 5; st++) {
        const int ls = 2 * st;
        const int s = 1 << ls;
        const int idx = v & ~(s - 1);   // p*s
        float2 w1 = tw[idx];
        float2 w2 = tw[2*idx];
        float2 w3 = tw[3*idx];
        float2 a = src[F(v)];
        float2 b = src[F(v + 256)];
        float2 c = src[F(v + 512)];
        float2 d = src[F(v + 768)];
        float2 apc = make_float2(a.x + c.x, a.y + c.y);
        float2 amc = make_float2(a.x - c.x, a.y - c.y);
        float2 bpd = make_float2(b.x + d.x, b.y + d.y);
        float2 jbmd = make_float2(-(b.y - d.y), b.x - d.x);   // i*(b-d)
        const int bo = v + 3 * idx;                            // q + 4sp
        dst[F(bo)]         = make_float2(apc.x + bpd.x, apc.y + bpd.y);
        dst[F(bo + s)]     = cmulf(w1, make_float2(amc.x - jbmd.x, amc.y - jbmd.y));
        dst[F(bo + 2*s)]   = cmulf(w2, make_float2(apc.x - bpd.x, apc.y - bpd.y));
        dst[F(bo + 3*s)]   = cmulf(w3, make_float2(amc.x + jbmd.x, amc.y + jbmd.y));
        __syncthreads();
        float2* tmp = src; src = dst; dst = tmp;
    }
}

// ---------------- forward FFTs: LN(q), LN(k); Kx = Xf*Kf; Qf ----------------
__global__ void __launch_bounds__(256) fft_fwd_kernel(
    const float* __restrict__ x,
    const float* __restrict__ gq, const float* __restrict__ betaq,
    const float* __restrict__ gk, const float* __restrict__ betak)
{
    const int row = blockIdx.x;
    const int t = threadIdx.x;
    __shared__ float2 tw[768];
    __shared__ float2 bufA[1024];
    __shared__ float2 bufB[1024];
    __shared__ float2 red2[8];

    #pragma unroll
    for (int j = 0; j < 3; j++) {
        int i = t + 256 * j;
        float s_, c_;
        sincospif((float)i * (1.0f/512.0f), &s_, &c_);
        tw[i] = make_float2(c_, -s_);
    }

    const float* xr = x    + (size_t)row * DIMS;
    const float* qr = g_qk + (size_t)row * 2 * DIMS;
    const float* kr = qr + DIMS;
    float xv[4], qv[4], kv[4];
    #pragma unroll
    for (int i = 0; i < 4; i++) {
        int e = t + 256 * i;
        xv[i] = xr[e]; qv[i] = qr[e]; kv[i] = kr[e];
    }

    const float invN = 1.0f / 1024.0f;
    float2 s1 = make_float2(0.f, 0.f), s2 = make_float2(0.f, 0.f);
    #pragma unroll
    for (int i = 0; i < 4; i++) {
        s1.x += qv[i]; s1.y += kv[i];
        s2.x += qv[i]*qv[i]; s2.y += kv[i]*kv[i];
    }
    s1 = block_sum2_256(s1, red2);
    s2 = block_sum2_256(s2, red2);
    float mq = s1.x * invN, vq = s2.x * invN - mq*mq;
    float rq = rsqrtf(vq + 1e-5f);
    float mk = s1.y * invN, vk = s2.y * invN - mk*mk;
    float rk = rsqrtf(vk + 1e-5f);

    float qn[4], kn[4];
    #pragma unroll
    for (int i = 0; i < 4; i++) {
        int e = t + 256 * i;
        qn[i] = (qv[i] - mq) * rq * gq[e] + betaq[e];
        kn[i] = (kv[i] - mk) * rk * gk[e] + betak[e];
    }

    // FFT of z = x + i*kn
    #pragma unroll
    for (int i = 0; i < 4; i++) bufA[F(t + 256*i)] = make_float2(xv[i], kn[i]);
    __syncthreads();
    fft1024_r4(bufA, bufB, tw, t);   // result in bufB

    // split Xf/Kf and write Kx for bins t and t+256; refill bufA for q-FFT
    {
        #pragma unroll
        for (int jj = 0; jj < 2; jj++) {
            int j = t + 256 * jj;
            float2 z  = bufB[F(j)];
            float2 zn = bufB[F((1024 - j) & 1023)];
            float2 xf = make_float2(0.5f*(z.x + zn.x), 0.5f*(z.y - zn.y));
            float2 df = make_float2(z.x - zn.x, z.y + zn.y);
            float2 kf = make_float2(0.5f*df.y, -0.5f*df.x);
            g_kx[(size_t)row*NF + j] = cmulf(xf, kf);
        }
        if (t == 0) {
            float2 z5 = bufB[F(512)];
            g_kx[(size_t)row*NF + 512] = make_float2(z5.x * z5.y, 0.f);
        }
    }
    #pragma unroll
    for (int i = 0; i < 4; i++) bufA[F(t + 256*i)] = make_float2(qn[i], 0.f);
    __syncthreads();
    fft1024_r4(bufA, bufB, tw, t);   // result in bufB

    #pragma unroll
    for (int jj = 0; jj < 2; jj++) {
        int j = t + 256 * jj;
        g_qf[(size_t)row*NF + j] = bufB[F(j)];
    }
    if (t == 0) g_qf[(size_t)row*NF + 512] = bufB[F(512)];
}

// ---------------- reduce S_freq[b] = sum_s Kx[b,s] ----------------
__global__ void __launch_bounds__(256) reduce_s_kernel() {
    const int b = blockIdx.x;
    const int j = blockIdx.y;
    const int t = threadIdx.x;
    float2 acc = make_float2(0.f, 0.f);
    const float2* p = g_kx + (size_t)b * SEQ * NF + j;
    for (int s = t; s < SEQ; s += 256) {
        float2 v = p[(size_t)s * NF];
        acc.x += v.x; acc.y += v.y;
    }
    __shared__ float2 red[256];
    red[t] = acc;
    __syncthreads();
    for (int o = 128; o; o >>= 1) {
        if (t < o) { red[t].x += red[t+o].x; red[t].y += red[t+o].y; }
        __syncthreads();
    }
    if (t == 0) g_sf[b * NF + j] = red[0];
}

// ---------------- inverse FFT of mixF = Kx + S*conj(Qf); LN(x + mix) ----------------
__global__ void __launch_bounds__(256) fft_inv_ln_kernel(
    const float* __restrict__ x,
    const float* __restrict__ g0, const float* __restrict__ beta0)
{
    const int row = blockIdx.x;
    const int b = row >> 12;
    const int t = threadIdx.x;
    __shared__ float2 tw[768];
    __shared__ float2 bufA[1024];
    __shared__ float2 bufB[1024];
    __shared__ float2 red2[8];

    #pragma unroll
    for (int j = 0; j < 3; j++) {
        int i = t + 256 * j;
        float s_, c_;
        sincospif((float)i * (1.0f/512.0f), &s_, &c_);
        tw[i] = make_float2(c_, -s_);
    }

    // build conj(mixF) full spectrum (ifft via forward fft of conjugate)
    #pragma unroll
    for (int jj = 0; jj < 2; jj++) {
        int j = t + 256 * jj;
        float2 kx = g_kx[(size_t)row*NF + j];
        float2 sf = g_sf[b*NF + j];
        float2 qf = g_qf[(size_t)row*NF + j];
        float2 qc = make_float2(qf.x, -qf.y);
        float2 p  = cmulf(sf, qc);
        float2 mv = make_float2(kx.x + p.x, kx.y + p.y);
        bufA[F(j)] = make_float2(mv.x, -mv.y);
        if (j > 0) bufA[F(1024 - j)] = mv;
    }
    if (t == 0) {
        float2 kx5 = g_kx[(size_t)row*NF + 512];
        float2 sf5 = g_sf[b*NF + 512];
        float2 qf5 = g_qf[(size_t)row*NF + 512];
        float2 qc5 = make_float2(qf5.x, -qf5.y);
        float2 p5  = cmulf(sf5, qc5);
        bufA[F(512)] = make_float2(kx5.x + p5.x, -(kx5.y + p5.y));
    }
    __syncthreads();
    fft1024_r4(bufA, bufB, tw, t);   // result in bufB

    const float invN = 1.0f / 1024.0f;
    const float* xr = x + (size_t)row * DIMS;
    float y[4];
    float2 s12 = make_float2(0.f, 0.f);
    #pragma unroll
    for (int i = 0; i < 4; i++) {
        int e = t + 256 * i;
        y[i] = xr[e] + bufB[F(e)].x * invN;
        s12.x += y[i];
        s12.y += y[i] * y[i];
    }
    s12 = block_sum2_256(s12, red2);
    float m = s12.x * invN, v = s12.y * invN - m*m;
    float r = rsqrtf(v + 1e-5f);
    float*  o  = g_x1  + (size_t)row * DIMS;
    __half* oh = g_x1h + (size_t)row * DIMS;
    #pragma unroll
    for (int i = 0; i < 4; i++) {
        int e = t + 256 * i;
        float ov = (y[i] - m) * r * g0[e] + beta0[e];
        o[e]  = ov;
        oh[e] = __float2half_rn(ov);
    }
}

// ---------------- out = LN(x1 + ff) ----------------
__device__ __forceinline__ float block_sum512(float v, volatile float* red) {
    int t = threadIdx.x;
    #pragma unroll
    for (int o = 16; o; o >>= 1) v += __shfl_xor_sync(0xffffffffu, v, o);
    if ((t & 31) == 0) red[t >> 5] = v;
    __syncthreads();
    if (t == 0) {
        float s = 0.f;
        #pragma unroll
        for (int i = 0; i < 16; i++) s += red[i];
        red[0] = s;
    }
    __syncthreads();
    float r = red[0];
    __syncthreads();
    return r;
}

__global__ void __launch_bounds__(512) resid_ln_kernel(
    const float* __restrict__ g1v, const float* __restrict__ beta1,
    float* __restrict__ out)
{
    const int row = blockIdx.x;
    const int t = threadIdx.x;
    __shared__ float red[16];
    const float* a = g_x1 + (size_t)row * DIMS;
    const float* f = g_ff + (size_t)row * DIMS;
    float y0 = a[t]     + f[t];
    float y1 = a[t+512] + f[t+512];
    const float invN = 1.0f / 1024.0f;
    float s  = block_sum512(y0 + y1, red);
    float ss = block_sum512(y0*y0 + y1*y1, red);
    float m = s * invN, v = ss * invN - m*m;
    float r = rsqrtf(v + 1e-5f);
    float* o = out + (size_t)row * DIMS;
    o[t]     = (y0 - m) * r * g1v[t]     + beta1[t];
    o[t+512] = (y1 - m) * r * g1v[t+512] + beta1[t+512];
}

// ---------------- launch ----------------
extern "C" void kernel_launch(void* const* d_in, const int* in_sizes, int n_in,
                              void* d_out, int out_size)
{
    const float* x     = (const float*)d_in[0];
    const float* Wq    = (const float*)d_in[1];
    const float* bq    = (const float*)d_in[2];
    const float* gq    = (const float*)d_in[3];
    const float* betaq = (const float*)d_in[4];
    const float* Wk    = (const float*)d_in[5];
    const float* bk    = (const float*)d_in[6];
    const float* gk    = (const float*)d_in[7];
    const float* betak = (const float*)d_in[8];
    const float* g0    = (const float*)d_in[9];
    const float* beta0 = (const float*)d_in[10];
    const float* W1    = (const float*)d_in[11];
    const float* b1    = (const float*)d_in[12];
    const float* W2    = (const float*)d_in[13];
    const float* b2    = (const float*)d_in[14];
    const float* g1    = (const float*)d_in[15];
    const float* beta1 = (const float*)d_in[16];
    float* out = (float*)d_out;

    float *pqk, *pff, *pbr;
    __half *px1h, *ph, *pxh, *pwh;
    cudaGetSymbolAddress((void**)&pqk,  g_qk);
    cudaGetSymbolAddress((void**)&px1h, g_x1h);
    cudaGetSymbolAddress((void**)&ph,   g_h);
    cudaGetSymbolAddress((void**)&pff,  g_ff);
    cudaGetSymbolAddress((void**)&pxh,  g_xh);
    cudaGetSymbolAddress((void**)&pwh,  g_wh);
    cudaGetSymbolAddress((void**)&pbr,  g_br);

    const int SMEM = NSTAGE * STAGE_BYTES;  // 165888 B
    cudaFuncSetAttribute(gemm_h<0,float>,  cudaFuncAttributeMaxDynamicSharedMemorySize, SMEM);
    cudaFuncSetAttribute(gemm_h<1,__half>, cudaFuncAttributeMaxDynamicSharedMemorySize, SMEM);

    // fp16 conversions (rn), pack Wq|Wk and bq|bk
    {
        int n;
        n = ROWS * DIMS / 8;   conv_h_kernel<<<(n+255)/256, 256>>>(x,  pxh, n);
        n = DIMS * DIMS / 8;   conv_h_kernel<<<(n+255)/256, 256>>>(Wq, pwh + WQK_OFF, n);
        n = DIMS * DIMS / 8;   conv_h_kernel<<<(n+255)/256, 256>>>(Wk, pwh + WQK_OFF + DIMS*DIMS, n);
        n = FFD * DIMS / 8;    conv_h_kernel<<<(n+255)/256, 256>>>(W1, pwh + W1_OFF, n);
        n = DIMS * FFD / 8;    conv_h_kernel<<<(n+255)/256, 256>>>(W2, pwh + W2_OFF, n);
        pack_bias_kernel<<<(DIMS+255)/256, 256>>>(bq, bk);
    }

    // [q|k] = x @ [Wq|Wk]^T + [bq|bk]   (fused, N=2048, fp16 MMA)
    gemm_h<0,float><<<dim3(2*DIMS/128, ROWS/256), 256, SMEM>>>(pxh, pwh + WQK_OFF, pbr, pqk, 2*DIMS, DIMS);
    // LN(q), LN(k), forward FFTs, Kx, Qf  (radix-4)
    fft_fwd_kernel<<<ROWS, 256>>>(x, gq, betaq, gk, betak);
    // S = sum_s Kx (freq domain)
    reduce_s_kernel<<<dim3(BATCH, NF), 256>>>();
    // mix = irfft(Kx + S*conj(Qf)); x1 = LN(x + mix) (+fp16 copy)
    fft_inv_ln_kernel<<<ROWS, 256>>>(x, g0, beta0);
    // h = relu(x1 @ W1^T + b1) -> fp16
    gemm_h<1,__half><<<dim3(FFD/128, ROWS/256), 256, SMEM>>>(px1h, pwh + W1_OFF, b1, ph, FFD, DIMS);
    // ff = h @ W2^T + b2
    gemm_h<0,float><<<dim3(DIMS/128, ROWS/256), 256, SMEM>>>(ph, pwh + W2_OFF, b2, pff, DIMS, FFD);
    // out = LN(x1 + ff)
    resid_ln_kernel<<<ROWS, 512>>>(g1, beta1, out);
}